// round 12
// baseline (speedup 1.0000x reference)
#include <cuda_runtime.h>
#include <cuda_bf16.h>
#include <math.h>

#define N_P   50000
#define N_HE  5000
#define D_IN  128
#define D_HID 256
#define N_HEADS 4
#define HEAD_DIM 64

#define HE_CAP 256
#define P_CAP  64
#define OVF_CAP 65536

// bf16 plane strides (in bf16 elems): row bytes odd multiple of 16
#define PB128 136
#define PB256 264

// packed-weight sections (u32), fragment-order layout (see pack kernel)
#define OFF_WSELF 0
#define OFF_WCLU  8192
#define OFF_WF1   16384
#define OFF_WF2   49152
#define OFF_WH1   65536
#define PACK_TOTAL 81920

// ---- scratch (no allocation allowed) ----
__device__ float g_he_feat[N_HE * D_IN];
__device__ float g_he_w[N_HE * D_IN];
__device__ float g_cluster[N_P * D_IN];
__device__ float g_selfclu[(size_t)N_P * 256];   // fp32 self_f|clu_f for stage E
__device__ int   g_cnt_he[N_HE];
__device__ int   g_cnt_p[N_P];
__device__ float2 g_list_he[N_HE * HE_CAP];
__device__ float2 g_list_p[N_P * P_CAP];
__device__ float4 g_ovf[OVF_CAP];
__device__ int   g_novf;
__device__ __align__(16) unsigned g_Whi[PACK_TOTAL];
__device__ __align__(16) unsigned g_Wlo[PACK_TOTAL];

// ---------------------------------------------------------------------------
__device__ __forceinline__ void red_add_v4(float* dst, float a, float b, float c, float d) {
    asm volatile("red.global.add.v4.f32 [%0], {%1,%2,%3,%4};"
                 :: "l"(dst), "f"(a), "f"(b), "f"(c), "f"(d) : "memory");
}

__device__ __forceinline__ void split_pack(float x0, float x1, unsigned& hi, unsigned& lo) {
    __nv_bfloat16 h0 = __float2bfloat16(x0);
    __nv_bfloat16 h1 = __float2bfloat16(x1);
    __nv_bfloat16 l0 = __float2bfloat16(x0 - __bfloat162float(h0));
    __nv_bfloat16 l1 = __float2bfloat16(x1 - __bfloat162float(h1));
    hi = (unsigned)__bfloat16_as_ushort(h0) | ((unsigned)__bfloat16_as_ushort(h1) << 16);
    lo = (unsigned)__bfloat16_as_ushort(l0) | ((unsigned)__bfloat16_as_ushort(l1) << 16);
}

// ---------------------------------------------------------------------------
// zero (he_feat + counters) fused with FRAGMENT-ORDER weight packing
// ---------------------------------------------------------------------------
__global__ void zero_pack_kernel(const float* __restrict__ Wself, const float* __restrict__ Wclu,
                                 const float* __restrict__ Wf1,   const float* __restrict__ Wf2,
                                 const float* __restrict__ Wh1) {
    int i = blockIdx.x * blockDim.x + threadIdx.x;
    if (i < N_HE * (D_IN / 4))
        ((float4*)g_he_feat)[i] = make_float4(0.f, 0.f, 0.f, 0.f);
    if (i < N_HE) g_cnt_he[i] = 0;
    if (i < N_P)  g_cnt_p[i] = 0;
    if (i == 0)   g_novf = 0;
    if (i < PACK_TOTAL) {
        const float* W;
        int N, K, NT, local;
        if (i < OFF_WCLU)      { W = Wself; N = 128; K = 128; NT = 4; local = i; }
        else if (i < OFF_WF1)  { W = Wclu;  N = 128; K = 128; NT = 4; local = i - OFF_WCLU; }
        else if (i < OFF_WF2)  { W = Wf1;   N = 256; K = 256; NT = 4; local = i - OFF_WF1; }
        else if (i < OFF_WH1)  { W = Wf2;   N = 128; K = 256; NT = 2; local = i - OFF_WF2; }
        else {
            local = i - OFF_WH1;
            int head = local / 4096; local -= head * 4096;
            W = Wh1 + (size_t)head * 128 * 64; N = 64; K = 128; NT = 4;
        }
        int KT = K / 16;
        int twoNT = 2 * NT;
        int j = local % twoNT;  int r = local / twoNT;
        int lane = r % 32;      r /= 32;
        int kt = r % KT;        int wb = r / KT;
        int tig = lane & 3, gid = lane >> 2;
        int nt = (j < NT) ? j : j - NT;
        int k2 = kt * 8 + ((j < NT) ? 0 : 4) + tig;
        int n  = wb * NT * 8 + nt * 8 + gid;
        unsigned hi, lo;
        split_pack(W[(size_t)(2 * k2) * N + n], W[(size_t)(2 * k2 + 1) * N + n], hi, lo);
        g_Whi[i] = hi;
        g_Wlo[i] = lo;
    }
}

// ---------------------------------------------------------------------------
__global__ void fill_kernel(const float* __restrict__ ew,
                            const int* __restrict__ pid,
                            const int* __restrict__ hid,
                            const float* __restrict__ feat, int nE) {
    int e = blockIdx.x * blockDim.x + threadIdx.x;
    if (e >= nE) return;
    int p = pid[e];
    int h = hid[e];
    float w = ew[e];

    int pos = atomicAdd(&g_cnt_he[h], 1);
    if (pos < HE_CAP) {
        g_list_he[(size_t)h * HE_CAP + pos] = make_float2(__int_as_float(p), w);
    } else {
        const float4* fr = (const float4*)(feat + (size_t)p * D_IN);
        for (int i = 0; i < D_IN / 4; i++) {
            float4 v = fr[i];
            red_add_v4(g_he_feat + (size_t)h * D_IN + i * 4,
                       v.x * w, v.y * w, v.z * w, v.w * w);
        }
    }

    int pos2 = atomicAdd(&g_cnt_p[p], 1);
    if (pos2 < P_CAP) {
        g_list_p[(size_t)p * P_CAP + pos2] = make_float2(__int_as_float(h), w);
    } else {
        int o = atomicAdd(&g_novf, 1);
        if (o < OVF_CAP)
            g_ovf[o] = make_float4(__int_as_float(p), __int_as_float(h), w, 0.f);
    }
}

// ---------------------------------------------------------------------------
__global__ void zero_cluster_kernel() {
    if (g_novf == 0) return;
    int i = blockIdx.x * blockDim.x + threadIdx.x;
    if (i < N_P * (D_IN / 4))
        ((float4*)g_cluster)[i] = make_float4(0.f, 0.f, 0.f, 0.f);
}

// ---------------------------------------------------------------------------
// he_acc: warp per hyperedge, float4 row loads (R10 form — measured best)
// ---------------------------------------------------------------------------
__global__ __launch_bounds__(256) void he_acc_kernel(const float* __restrict__ feat) {
    __shared__ float2 s_list[8][HE_CAP];
    int wid = threadIdx.x >> 5, lane = threadIdx.x & 31;
    int he = blockIdx.x * 8 + wid;
    if (he >= N_HE) return;
    int n_raw = g_cnt_he[he];
    int n = n_raw < HE_CAP ? n_raw : HE_CAP;
    for (int i = lane; i < n; i += 32) s_list[wid][i] = g_list_he[(size_t)he * HE_CAP + i];
    __syncwarp();

    float4 acc = make_float4(0.f, 0.f, 0.f, 0.f);
    if (n_raw > HE_CAP)
        acc = ((const float4*)(g_he_feat + (size_t)he * D_IN))[lane];

    const float4* feat4 = (const float4*)feat;
    int i = 0;
    for (; i + 4 <= n; i += 4) {
        float2 e0 = s_list[wid][i],     e1 = s_list[wid][i + 1];
        float2 e2 = s_list[wid][i + 2], e3 = s_list[wid][i + 3];
        float4 v0 = feat4[(size_t)__float_as_int(e0.x) * 32 + lane];
        float4 v1 = feat4[(size_t)__float_as_int(e1.x) * 32 + lane];
        float4 v2 = feat4[(size_t)__float_as_int(e2.x) * 32 + lane];
        float4 v3 = feat4[(size_t)__float_as_int(e3.x) * 32 + lane];
        acc.x += e0.y * v0.x; acc.y += e0.y * v0.y; acc.z += e0.y * v0.z; acc.w += e0.y * v0.w;
        acc.x += e1.y * v1.x; acc.y += e1.y * v1.y; acc.z += e1.y * v1.z; acc.w += e1.y * v1.w;
        acc.x += e2.y * v2.x; acc.y += e2.y * v2.y; acc.z += e2.y * v2.z; acc.w += e2.y * v2.w;
        acc.x += e3.y * v3.x; acc.y += e3.y * v3.y; acc.z += e3.y * v3.z; acc.w += e3.y * v3.w;
    }
    for (; i < n; i++) {
        float2 e0 = s_list[wid][i];
        float4 v0 = feat4[(size_t)__float_as_int(e0.x) * 32 + lane];
        acc.x += e0.y * v0.x; acc.y += e0.y * v0.y; acc.z += e0.y * v0.z; acc.w += e0.y * v0.w;
    }
    ((float4*)(g_he_feat + (size_t)he * D_IN))[lane] = acc;
}

// ---------------------------------------------------------------------------
// bf16 MMA machinery; B fragment-packed (LDG.128), A single-buffered LDSM
// ---------------------------------------------------------------------------
__device__ __forceinline__ void mma_bf16(float (&c)[4], const unsigned (&a)[4],
                                         unsigned b0, unsigned b1) {
    asm volatile(
        "mma.sync.aligned.m16n8k16.row.col.f32.bf16.bf16.f32 "
        "{%0,%1,%2,%3},{%4,%5,%6,%7},{%8,%9},{%0,%1,%2,%3};\n"
        : "+f"(c[0]), "+f"(c[1]), "+f"(c[2]), "+f"(c[3])
        : "r"(a[0]), "r"(a[1]), "r"(a[2]), "r"(a[3]), "r"(b0), "r"(b1));
}

#define LDSM4(R, ADDR) \
    asm volatile("ldmatrix.sync.aligned.m8n8.x4.shared.b16 {%0,%1,%2,%3},[%4];" \
                 : "=r"((R)[0]), "=r"((R)[1]), "=r"((R)[2]), "=r"((R)[3]) : "r"(ADDR))

__device__ __forceinline__ unsigned smem_u32(const void* p) {
    return (unsigned)__cvta_generic_to_shared(p);
}

template <int KT, int NT, int MT>
__device__ __forceinline__ void gemm_bf16(const unsigned (&aAddr)[MT], unsigned loOffBytes,
                                          const uint4* __restrict__ Bhi,
                                          const uint4* __restrict__ Blo,
                                          float (&acc)[MT][NT][4]) {
    constexpr int NB4 = NT / 2;
    unsigned bh0[2 * NT], bl0[2 * NT];
#pragma unroll
    for (int q = 0; q < NB4; q++) {
        uint4 vh = __ldg(Bhi + q), vl = __ldg(Blo + q);
        bh0[4 * q + 0] = vh.x; bh0[4 * q + 1] = vh.y; bh0[4 * q + 2] = vh.z; bh0[4 * q + 3] = vh.w;
        bl0[4 * q + 0] = vl.x; bl0[4 * q + 1] = vl.y; bl0[4 * q + 2] = vl.z; bl0[4 * q + 3] = vl.w;
    }
#pragma unroll
    for (int kt = 0; kt < KT; kt++) {
        unsigned ah0[MT][4], al0[MT][4];
#pragma unroll
        for (int mt = 0; mt < MT; mt++) {
            LDSM4(ah0[mt], aAddr[mt] + kt * 32u);
            LDSM4(al0[mt], aAddr[mt] + loOffBytes + kt * 32u);
        }
        unsigned bh1[2 * NT], bl1[2 * NT];
        if (kt + 1 < KT) {
#pragma unroll
            for (int q = 0; q < NB4; q++) {
                uint4 vh = __ldg(Bhi + (size_t)(kt + 1) * 32 * NB4 + q);
                uint4 vl = __ldg(Blo + (size_t)(kt + 1) * 32 * NB4 + q);
                bh1[4 * q + 0] = vh.x; bh1[4 * q + 1] = vh.y; bh1[4 * q + 2] = vh.z; bh1[4 * q + 3] = vh.w;
                bl1[4 * q + 0] = vl.x; bl1[4 * q + 1] = vl.y; bl1[4 * q + 2] = vl.z; bl1[4 * q + 3] = vl.w;
            }
        }
#pragma unroll
        for (int nt = 0; nt < NT; nt++)
#pragma unroll
            for (int mt = 0; mt < MT; mt++) {
                mma_bf16(acc[mt][nt], al0[mt], bh0[nt], bh0[NT + nt]);
                mma_bf16(acc[mt][nt], ah0[mt], bl0[nt], bl0[NT + nt]);
                mma_bf16(acc[mt][nt], ah0[mt], bh0[nt], bh0[NT + nt]);
            }
#pragma unroll
        for (int j = 0; j < 2 * NT; j++) { bh0[j] = bh1[j]; bl0[j] = bl1[j]; }
    }
}

template <int NT, int MT, bool RELU>
__device__ __forceinline__ void epilogue_f32(float* dst, int dstride, int col0,
                                             const float* __restrict__ bias,
                                             float (&acc)[MT][NT][4], int lane) {
    int gid = lane >> 2, tig = lane & 3;
#pragma unroll
    for (int nt = 0; nt < NT; nt++) {
        int c = nt * 8 + tig * 2;
        float bA = __ldg(bias + c), bB = __ldg(bias + c + 1);
#pragma unroll
        for (int mt = 0; mt < MT; mt++) {
            int r = mt * 16 + gid;
            float v0 = acc[mt][nt][0] + bA, v1 = acc[mt][nt][1] + bB;
            float v2 = acc[mt][nt][2] + bA, v3 = acc[mt][nt][3] + bB;
            if (RELU) {
                v0 = fmaxf(v0, 0.f); v1 = fmaxf(v1, 0.f);
                v2 = fmaxf(v2, 0.f); v3 = fmaxf(v3, 0.f);
            }
            dst[(size_t)r * dstride + col0 + c]           = v0;
            dst[(size_t)r * dstride + col0 + c + 1]       = v1;
            dst[(size_t)(r + 8) * dstride + col0 + c]     = v2;
            dst[(size_t)(r + 8) * dstride + col0 + c + 1] = v3;
        }
    }
}

template <int NT, int MT, bool RELU>
__device__ __forceinline__ void epilogue_bf16(unsigned short* hiBase, int strideElems,
                                              int loOffElems, int col0,
                                              const float* __restrict__ bias,
                                              float (&acc)[MT][NT][4], int lane) {
    int gid = lane >> 2, tig = lane & 3;
#pragma unroll
    for (int nt = 0; nt < NT; nt++) {
        int c = nt * 8 + tig * 2;
        float bA = __ldg(bias + c), bB = __ldg(bias + c + 1);
#pragma unroll
        for (int mt = 0; mt < MT; mt++) {
            int r = mt * 16 + gid;
            float v0 = acc[mt][nt][0] + bA, v1 = acc[mt][nt][1] + bB;
            float v2 = acc[mt][nt][2] + bA, v3 = acc[mt][nt][3] + bB;
            if (RELU) {
                v0 = fmaxf(v0, 0.f); v1 = fmaxf(v1, 0.f);
                v2 = fmaxf(v2, 0.f); v3 = fmaxf(v3, 0.f);
            }
            unsigned h01, l01, h23, l23;
            split_pack(v0, v1, h01, l01);
            split_pack(v2, v3, h23, l23);
            int i0 = r * strideElems + col0 + c;
            int i1 = (r + 8) * strideElems + col0 + c;
            *(unsigned*)&hiBase[i0]               = h01;
            *(unsigned*)&hiBase[loOffElems + i0]  = l01;
            *(unsigned*)&hiBase[i1]               = h23;
            *(unsigned*)&hiBase[loOffElems + i1]  = l23;
        }
    }
}

// stage-A epilogue: bf16 planes (for stage B) + exact fp32 to gmem (for stage E)
template <int NT, int MT>
__device__ __forceinline__ void epilogue_a(unsigned short* hiBase, int strideElems,
                                           int loOffElems, int col0,
                                           float* __restrict__ gdst, int row0, int nP,
                                           const float* __restrict__ bias,
                                           float (&acc)[MT][NT][4], int lane) {
    int gid = lane >> 2, tig = lane & 3;
#pragma unroll
    for (int nt = 0; nt < NT; nt++) {
        int c = nt * 8 + tig * 2;
        float bA = __ldg(bias + c), bB = __ldg(bias + c + 1);
#pragma unroll
        for (int mt = 0; mt < MT; mt++) {
            int r = mt * 16 + gid;
            float v0 = acc[mt][nt][0] + bA, v1 = acc[mt][nt][1] + bB;
            float v2 = acc[mt][nt][2] + bA, v3 = acc[mt][nt][3] + bB;
            unsigned h01, l01, h23, l23;
            split_pack(v0, v1, h01, l01);
            split_pack(v2, v3, h23, l23);
            int i0 = r * strideElems + col0 + c;
            int i1 = (r + 8) * strideElems + col0 + c;
            *(unsigned*)&hiBase[i0]               = h01;
            *(unsigned*)&hiBase[loOffElems + i0]  = l01;
            *(unsigned*)&hiBase[i1]               = h23;
            *(unsigned*)&hiBase[loOffElems + i1]  = l23;
            if (row0 + r < nP) {
                float* g0 = gdst + (size_t)(row0 + r) * 256 + col0 + c;
                g0[0] = v0; g0[1] = v1;
            }
            if (row0 + r + 8 < nP) {
                float* g1 = gdst + (size_t)(row0 + r + 8) * 256 + col0 + c;
                g1[0] = v2; g1[1] = v3;
            }
        }
    }
}

__device__ __forceinline__ void load_tile_planes(unsigned short* plane, int strideElems,
                                                 int loOffElems, const float4* src,
                                                 int row0, int rowMax, int t) {
    for (int i = t; i < 32 * 32; i += 256) {
        int r = i >> 5, c4 = i & 31;
        int gr = row0 + r;
        float4 v = make_float4(0.f, 0.f, 0.f, 0.f);
        if (gr < rowMax) v = src[(size_t)gr * 32 + c4];
        unsigned h01, l01, h23, l23;
        split_pack(v.x, v.y, h01, l01);
        split_pack(v.z, v.w, h23, l23);
        int base = r * strideElems + c4 * 4;
        *(unsigned*)&plane[base]                   = h01;
        *(unsigned*)&plane[base + 2]               = h23;
        *(unsigned*)&plane[loOffElems + base]      = l01;
        *(unsigned*)&plane[loOffElems + base + 2]  = l23;
    }
}

// ---------------------------------------------------------------------------
// attention: 32-row tiles, bf16-split GEMM vs fragment-packed Wh1 (unchanged)
// ---------------------------------------------------------------------------
__global__ __launch_bounds__(256) void attn_gemm_kernel(
    const float* __restrict__ bh1, const float* __restrict__ Wh2,
    const float* __restrict__ bh2, const float* __restrict__ Wfuse) {
    __shared__ unsigned short s_he[2 * 32 * PB128];
    __shared__ float s_part[32][8];
    __shared__ float s_attn[32];

    int row0 = blockIdx.x * 32;
    int t = threadIdx.x, wid = t >> 5, lane = t & 31;

    load_tile_planes(s_he, PB128, 32 * PB128, (const float4*)g_he_feat, row0, N_HE, t);
    __syncthreads();

    int m8 = lane >> 3, rIn = lane & 7;
    int rowoff = (m8 & 1) * 8 + rIn;
    int colByte = (m8 >> 1) * 16;
    int gid = lane >> 2, tig = lane & 3;

    int head = wid >> 1;
    int colHalf = (wid & 1) * 32;

    float acc[2][4][4];
#pragma unroll
    for (int a = 0; a < 2; a++)
#pragma unroll
        for (int b = 0; b < 4; b++)
#pragma unroll
            for (int c = 0; c < 4; c++) acc[a][b][c] = 0.f;

    unsigned aAddr[2];
#pragma unroll
    for (int mt = 0; mt < 2; mt++)
        aAddr[mt] = smem_u32(s_he + (mt * 16 + rowoff) * PB128) + colByte;

    size_t fidx = ((size_t)((wid & 1) * 8) * 32 + lane) * 2;
    const uint4* Bhi = (const uint4*)(g_Whi + OFF_WH1 + head * 4096) + fidx;
    const uint4* Blo = (const uint4*)(g_Wlo + OFF_WH1 + head * 4096) + fidx;
    gemm_bf16<8, 4, 2>(aAddr, 32 * PB128 * 2, Bhi, Blo, acc);

    float p0[2] = {0.f, 0.f};
    float p1[2] = {0.f, 0.f};
#pragma unroll
    for (int nt = 0; nt < 4; nt++) {
        int c = head * HEAD_DIM + colHalf + nt * 8 + tig * 2;
        float bA = __ldg(bh1 + c),  bB = __ldg(bh1 + c + 1);
        float wA = __ldg(Wh2 + c),  wB = __ldg(Wh2 + c + 1);
#pragma unroll
        for (int mt = 0; mt < 2; mt++) {
            p0[mt] += fmaxf(acc[mt][nt][0] + bA, 0.f) * wA
                    + fmaxf(acc[mt][nt][1] + bB, 0.f) * wB;
            p1[mt] += fmaxf(acc[mt][nt][2] + bA, 0.f) * wA
                    + fmaxf(acc[mt][nt][3] + bB, 0.f) * wB;
        }
    }
#pragma unroll
    for (int mt = 0; mt < 2; mt++) {
        p0[mt] += __shfl_xor_sync(0xffffffffu, p0[mt], 1);
        p0[mt] += __shfl_xor_sync(0xffffffffu, p0[mt], 2);
        p1[mt] += __shfl_xor_sync(0xffffffffu, p1[mt], 1);
        p1[mt] += __shfl_xor_sync(0xffffffffu, p1[mt], 2);
    }
    if (tig == 0) {
#pragma unroll
        for (int mt = 0; mt < 2; mt++) {
            s_part[mt * 16 + gid][wid]     = p0[mt];
            s_part[mt * 16 + gid + 8][wid] = p1[mt];
        }
    }
    __syncthreads();

    if (t < 32) {
        float a = 0.f;
#pragma unroll
        for (int h = 0; h < N_HEADS; h++) {
            float logit = s_part[t][2 * h] + s_part[t][2 * h + 1] + __ldg(bh2 + h);
            a += __ldg(Wfuse + h) / (1.f + expf(-logit));
        }
        s_attn[t] = a;
    }
    __syncthreads();

    for (int i = t; i < 32 * 32; i += 256) {
        int r = i >> 5, c4 = i & 31;
        int gr = row0 + r;
        if (gr < N_HE) {
            float4 v = ((const float4*)g_he_feat)[(size_t)gr * 32 + c4];
            float a = s_attn[r];
            v.x *= a; v.y *= a; v.z *= a; v.w *= a;
            ((float4*)g_he_w)[(size_t)gr * 32 + c4] = v;
        }
    }
}

// ---------------------------------------------------------------------------
__global__ void ovf_kernel() {
    int novf = g_novf;
    if (novf > OVF_CAP) novf = OVF_CAP;
    int widg = (blockIdx.x * blockDim.x + threadIdx.x) >> 5;
    int lane = threadIdx.x & 31;
    int nw = (gridDim.x * blockDim.x) >> 5;
    for (int e = widg; e < novf; e += nw) {
        float4 o = g_ovf[e];
        int p = __float_as_int(o.x);
        int h = __float_as_int(o.y);
        float w = o.z;
        float4 v = ((const float4*)(g_he_w + (size_t)h * D_IN))[lane];
        red_add_v4(g_cluster + (size_t)p * D_IN + lane * 4,
                   v.x * w, v.y * w, v.z * w, v.w * w);
    }
}

// ---------------------------------------------------------------------------
__global__ __launch_bounds__(256) void p_acc_kernel(int nP) {
    __shared__ float2 s_list[8][P_CAP];
    int wid = threadIdx.x >> 5, lane = threadIdx.x & 31;
    int p = blockIdx.x * 8 + wid;
    if (p >= nP) return;
    int n = g_cnt_p[p];
    if (n > P_CAP) n = P_CAP;
    for (int i = lane; i < n; i += 32) s_list[wid][i] = g_list_p[(size_t)p * P_CAP + i];
    __syncwarp();

    float4 acc = make_float4(0.f, 0.f, 0.f, 0.f);
    if (g_novf > 0)
        acc = ((const float4*)(g_cluster + (size_t)p * D_IN))[lane];

    const float4* hw4 = (const float4*)g_he_w;
    int i = 0;
    for (; i + 4 <= n; i += 4) {
        float2 e0 = s_list[wid][i],     e1 = s_list[wid][i + 1];
        float2 e2 = s_list[wid][i + 2], e3 = s_list[wid][i + 3];
        float4 v0 = hw4[(size_t)__float_as_int(e0.x) * 32 + lane];
        float4 v1 = hw4[(size_t)__float_as_int(e1.x) * 32 + lane];
        float4 v2 = hw4[(size_t)__float_as_int(e2.x) * 32 + lane];
        float4 v3 = hw4[(size_t)__float_as_int(e3.x) * 32 + lane];
        acc.x += e0.y * v0.x; acc.y += e0.y * v0.y; acc.z += e0.y * v0.z; acc.w += e0.y * v0.w;
        acc.x += e1.y * v1.x; acc.y += e1.y * v1.y; acc.z += e1.y * v1.z; acc.w += e1.y * v1.w;
        acc.x += e2.y * v2.x; acc.y += e2.y * v2.y; acc.z += e2.y * v2.z; acc.w += e2.y * v2.w;
        acc.x += e3.y * v3.x; acc.y += e3.y * v3.y; acc.z += e3.y * v3.z; acc.w += e3.y * v3.w;
    }
    for (; i < n; i++) {
        float2 e0 = s_list[wid][i];
        float4 v0 = hw4[(size_t)__float_as_int(e0.x) * 32 + lane];
        acc.x += e0.y * v0.x; acc.y += e0.y * v0.y; acc.z += e0.y * v0.z; acc.w += e0.y * v0.w;
    }
    ((float4*)(g_cluster + (size_t)p * D_IN))[lane] = acc;
}

// ---------------------------------------------------------------------------
// fused MLP, bf16-split, 32 rows/block, 68.9 KB smem -> 3 blocks/SM.
// smem (u16 elems):
//   X @0:      feat planes 2x(32xPB128) = 8704  -> x1 planes (2x32xPB256=16896) use X+Y
//   Y @8704:   clu planes  2x(32xPB128) = 8704
//   R3 @17408: cat planes  2x(32xPB256) = 16896 -> x2 fp32 (32x132=4224 f = 8448 u16)
//   gate @34304: float[32][2]
// self_f/clu_f fp32 for stage E go to gmem scratch g_selfclu.
// ---------------------------------------------------------------------------
#define XOFF 0
#define YOFF 8704
#define R3OFF 17408
#define GATEOFF 34304
#define LOP128 (32 * PB128)
#define LOP256 (32 * PB256)
#define SMEM_ELEMS (GATEOFF + 128)

__global__ __launch_bounds__(256, 3) void mlp2_kernel(
    const float* __restrict__ feat,
    const float* __restrict__ bself, const float* __restrict__ bclu,
    const float* __restrict__ bf1,   const float* __restrict__ bf2,
    const float* __restrict__ Wf3,   const float* __restrict__ bf3,
    float* __restrict__ out, int nP) {
    extern __shared__ unsigned short s16[];
    unsigned short* rX = s16 + XOFF;     // feat planes, later x1 (with Y)
    unsigned short* rY = s16 + YOFF;     // clu planes
    unsigned short* r3 = s16 + R3OFF;    // cat planes, later x2 fp32
    float (*s_gate)[2] = (float (*)[2])(s16 + GATEOFF);
    float* s_x2 = (float*)r3;            // fp32 overlay after stage B reads done

    int row0 = blockIdx.x * 32;
    int t = threadIdx.x;
    int wid = t >> 5, lane = t & 31;

    load_tile_planes(rX, PB128, LOP128, (const float4*)feat, row0, nP, t);
    load_tile_planes(rY, PB128, LOP128, (const float4*)g_cluster, row0, nP, t);
    __syncthreads();

    int m8 = lane >> 3, rIn = lane & 7;
    int rowoff = (m8 & 1) * 8 + rIn;
    int colByte = (m8 >> 1) * 16;
    int gid = lane >> 2, tig = lane & 3;

    // stage A: self_f | clu_f  (warps 0-3 self from rX, 4-7 clu from rY)
    {
        float acc[2][4][4];
#pragma unroll
        for (int a = 0; a < 2; a++)
#pragma unroll
            for (int b = 0; b < 4; b++)
#pragma unroll
                for (int c = 0; c < 4; c++) acc[a][b][c] = 0.f;

        unsigned short* aBuf = (wid < 4) ? rX : rY;
        int wOff             = (wid < 4) ? OFF_WSELF : OFF_WCLU;
        const float* bias    = (wid < 4) ? bself : bclu;
        int ncol0            = (wid & 3) * 32;
        int outcol0          = (wid < 4) ? ncol0 : (128 + ncol0);

        unsigned aAddr[2];
#pragma unroll
        for (int mt = 0; mt < 2; mt++)
            aAddr[mt] = smem_u32(aBuf + (mt * 16 + rowoff) * PB128) + colByte;

        size_t fidx = ((size_t)((wid & 3) * 8) * 32 + lane) * 2;
        const uint4* Bhi = (const uint4*)(g_Whi + wOff) + fidx;
        const uint4* Blo = (const uint4*)(g_Wlo + wOff) + fidx;
        gemm_bf16<8, 4, 2>(aAddr, LOP128 * 2, Bhi, Blo, acc);
        __syncthreads();
        epilogue_a<4, 2>(r3, PB256, LOP256, outcol0, g_selfclu, row0, nP,
                         bias + ncol0, acc, lane);
    }
    __syncthreads();

    // stage B: x1 = relu(cat @ Wf1 + bf1) -> planes over X+Y region
    {
        float acc[2][4][4];
#pragma unroll
        for (int a = 0; a < 2; a++)
#pragma unroll
            for (int b = 0; b < 4; b++)
#pragma unroll
                for (int c = 0; c < 4; c++) acc[a][b][c] = 0.f;

        int ncol0 = wid * 32;
        unsigned aAddr[2];
#pragma unroll
        for (int mt = 0; mt < 2; mt++)
            aAddr[mt] = smem_u32(r3 + (mt * 16 + rowoff) * PB256) + colByte;
        size_t fidx = ((size_t)(wid * 16) * 32 + lane) * 2;
        const uint4* Bhi = (const uint4*)(g_Whi + OFF_WF1) + fidx;
        const uint4* Blo = (const uint4*)(g_Wlo + OFF_WF1) + fidx;
        gemm_bf16<16, 4, 2>(aAddr, LOP256 * 2, Bhi, Blo, acc);
        __syncthreads();   // all reads of rX/rY planes done (stage A)
        epilogue_bf16<4, 2, true>(rX, PB256, LOP256, ncol0, bf1 + ncol0, acc, lane);
    }
    __syncthreads();

    // stage C: x2 = relu(x1 @ Wf2 + bf2) -> fp32 overlay on r3
    {
        float acc[2][2][4];
#pragma unroll
        for (int a = 0; a < 2; a++)
#pragma unroll
            for (int b = 0; b < 2; b++)
#pragma unroll
                for (int c = 0; c < 4; c++) acc[a][b][c] = 0.f;

        int ncol0 = wid * 16;
        unsigned aAddr[2];
#pragma unroll
        for (int mt = 0; mt < 2; mt++)
            aAddr[mt] = smem_u32(rX + (mt * 16 + rowoff) * PB256) + colByte;
        size_t fidx = ((size_t)(wid * 16) * 32 + lane) * 1;
        const uint4* Bhi = (const uint4*)(g_Whi + OFF_WF2) + fidx;
        const uint4* Blo = (const uint4*)(g_Wlo + OFF_WF2) + fidx;
        gemm_bf16<16, 2, 2>(aAddr, LOP256 * 2, Bhi, Blo, acc);
        __syncthreads();   // all reads of r3 (cat) done (stage B)
        epilogue_f32<2, 2, true>(s_x2, 132, ncol0, bf2 + ncol0, acc, lane);
    }
    __syncthreads();

    // stage D: logits + softmax gates
    if (t < 64) {
        int r = t >> 1, l = t & 1;
        float a = __ldg(bf3 + l);
        const float* x = s_x2 + (size_t)r * 132;
#pragma unroll 4
        for (int k = 0; k < 128; k++)
            a += x[k] * __ldg(Wf3 + 2 * k + l);
        s_gate[r][l] = a;
    }
    __syncthreads();
    if (t < 32) {
        float a = s_gate[t][0], b = s_gate[t][1];
        float m = fmaxf(a, b);
        float e0 = expf(a - m), e1 = expf(b - m);
        float inv = 1.f / (e0 + e1);
        s_gate[t][0] = e0 * inv;
        s_gate[t][1] = e1 * inv;
    }
    __syncthreads();

    // stage E: out = relu(self*g0 + clu*g1 + feat) from exact fp32 gmem scratch
    const float4* feat4 = (const float4*)feat;
    const float4* sc4 = (const float4*)g_selfclu;
    for (int i = t; i < 32 * 32; i += 256) {
        int r = i >> 5, c4 = i & 31;
        int gr = row0 + r;
        if (gr < nP) {
            float4 f  = feat4[(size_t)gr * 32 + c4];
            float4 sf = sc4[(size_t)gr * 64 + c4];
            float4 cf = sc4[(size_t)gr * 64 + 32 + c4];
            float g0 = s_gate[r][0], g1 = s_gate[r][1];
            float4 o;
            o.x = fmaxf(sf.x * g0 + cf.x * g1 + f.x, 0.f);
            o.y = fmaxf(sf.y * g0 + cf.y * g1 + f.y, 0.f);
            o.z = fmaxf(sf.z * g0 + cf.z * g1 + f.z, 0.f);
            o.w = fmaxf(sf.w * g0 + cf.w * g1 + f.w, 0.f);
            ((float4*)out)[(size_t)gr * 32 + c4] = o;
        }
    }
}

// ---------------------------------------------------------------------------
extern "C" void kernel_launch(void* const* d_in, const int* in_sizes, int n_in,
                              void* d_out, int out_size) {
    const float* feat   = (const float*)d_in[0];
    const float* edge_w = (const float*)d_in[1];
    const float* Wself  = (const float*)d_in[2];
    const float* bself  = (const float*)d_in[3];
    const float* Wclu   = (const float*)d_in[4];
    const float* bclu   = (const float*)d_in[5];
    const float* Wh1    = (const float*)d_in[6];
    const float* bh1    = (const float*)d_in[7];
    const float* Wh2    = (const float*)d_in[8];
    const float* bh2    = (const float*)d_in[9];
    const float* Wfuse  = (const float*)d_in[10];
    const float* Wf1    = (const float*)d_in[11];
    const float* bf1    = (const float*)d_in[12];
    const float* Wf2    = (const float*)d_in[13];
    const float* bf2    = (const float*)d_in[14];
    const float* Wf3    = (const float*)d_in[15];
    const float* bf3    = (const float*)d_in[16];
    const int*   e_pid  = (const int*)d_in[17];
    const int*   e_hid  = (const int*)d_in[18];

    int nE = in_sizes[17];
    int nP = in_sizes[0] / D_IN;
    float* out = (float*)d_out;

    int zpN = N_HE * (D_IN / 4);
    zero_pack_kernel<<<(zpN + 255) / 256, 256>>>(Wself, Wclu, Wf1, Wf2, Wh1);

    fill_kernel<<<(nE + 255) / 256, 256>>>(edge_w, e_pid, e_hid, feat, nE);

    zero_cluster_kernel<<<(N_P * (D_IN / 4) + 255) / 256, 256>>>();

    he_acc_kernel<<<(N_HE + 7) / 8, 256>>>(feat);

    attn_gemm_kernel<<<(N_HE + 31) / 32, 256>>>(bh1, Wh2, bh2, Wfuse);

    ovf_kernel<<<32, 256>>>();

    p_acc_kernel<<<(nP + 7) / 8, 256>>>(nP);

    size_t smemBytes = (size_t)SMEM_ELEMS * 2;
    cudaFuncSetAttribute(mlp2_kernel, cudaFuncAttributeMaxDynamicSharedMemorySize,
                         (int)smemBytes);
    int nBlocks = (nP + 31) / 32;
    mlp2_kernel<<<nBlocks, 256, smemBytes>>>(feat, bself, bclu, bf1, bf2,
                                             Wf3, bf3, out, nP);
}

// round 13
// speedup vs baseline: 1.0111x; 1.0111x over previous
#include <cuda_runtime.h>
#include <cuda_bf16.h>
#include <math.h>

#define N_P   50000
#define N_HE  5000
#define D_IN  128
#define D_HID 256
#define N_HEADS 4
#define HEAD_DIM 64

#define HE_CAP 256
#define P_CAP  64
#define OVF_CAP 65536

// bf16 plane strides (in bf16 elems): row bytes odd multiple of 16
#define PB128 136
#define PB256 264

// packed-weight sections (u32), fragment-order layout (see pack kernel)
#define OFF_WSELF 0
#define OFF_WCLU  8192
#define OFF_WF1   16384
#define OFF_WF2   49152
#define OFF_WH1   65536
#define PACK_TOTAL 81920

// ---- scratch (no allocation allowed) ----
__device__ float g_he_feat[N_HE * D_IN];
__device__ float g_he_w[N_HE * D_IN];
__device__ float g_cluster[N_P * D_IN];
__device__ int   g_cnt_he[N_HE];
__device__ int   g_cnt_p[N_P];
__device__ float2 g_list_he[N_HE * HE_CAP];
__device__ float2 g_list_p[N_P * P_CAP];
__device__ float4 g_ovf[OVF_CAP];
__device__ int   g_novf;
__device__ __align__(16) unsigned g_Whi[PACK_TOTAL];
__device__ __align__(16) unsigned g_Wlo[PACK_TOTAL];

// ---------------------------------------------------------------------------
__device__ __forceinline__ void red_add_v4(float* dst, float a, float b, float c, float d) {
    asm volatile("red.global.add.v4.f32 [%0], {%1,%2,%3,%4};"
                 :: "l"(dst), "f"(a), "f"(b), "f"(c), "f"(d) : "memory");
}

__device__ __forceinline__ void split_pack(float x0, float x1, unsigned& hi, unsigned& lo) {
    __nv_bfloat16 h0 = __float2bfloat16(x0);
    __nv_bfloat16 h1 = __float2bfloat16(x1);
    __nv_bfloat16 l0 = __float2bfloat16(x0 - __bfloat162float(h0));
    __nv_bfloat16 l1 = __float2bfloat16(x1 - __bfloat162float(h1));
    hi = (unsigned)__bfloat16_as_ushort(h0) | ((unsigned)__bfloat16_as_ushort(h1) << 16);
    lo = (unsigned)__bfloat16_as_ushort(l0) | ((unsigned)__bfloat16_as_ushort(l1) << 16);
}

__device__ __forceinline__ float bfu(unsigned short u) {
    return __bfloat162float(__ushort_as_bfloat16(u));
}

// ---------------------------------------------------------------------------
// zero (he_feat + counters) fused with FRAGMENT-ORDER weight packing
// ---------------------------------------------------------------------------
__global__ void zero_pack_kernel(const float* __restrict__ Wself, const float* __restrict__ Wclu,
                                 const float* __restrict__ Wf1,   const float* __restrict__ Wf2,
                                 const float* __restrict__ Wh1) {
    int i = blockIdx.x * blockDim.x + threadIdx.x;
    if (i < N_HE * (D_IN / 4))
        ((float4*)g_he_feat)[i] = make_float4(0.f, 0.f, 0.f, 0.f);
    if (i < N_HE) g_cnt_he[i] = 0;
    if (i < N_P)  g_cnt_p[i] = 0;
    if (i == 0)   g_novf = 0;
    if (i < PACK_TOTAL) {
        const float* W;
        int N, K, NT, local;
        if (i < OFF_WCLU)      { W = Wself; N = 128; K = 128; NT = 4; local = i; }
        else if (i < OFF_WF1)  { W = Wclu;  N = 128; K = 128; NT = 4; local = i - OFF_WCLU; }
        else if (i < OFF_WF2)  { W = Wf1;   N = 256; K = 256; NT = 4; local = i - OFF_WF1; }
        else if (i < OFF_WH1)  { W = Wf2;   N = 128; K = 256; NT = 2; local = i - OFF_WF2; }
        else {
            local = i - OFF_WH1;
            int head = local / 4096; local -= head * 4096;
            W = Wh1 + (size_t)head * 128 * 64; N = 64; K = 128; NT = 4;
        }
        int KT = K / 16;
        int twoNT = 2 * NT;
        int j = local % twoNT;  int r = local / twoNT;
        int lane = r % 32;      r /= 32;
        int kt = r % KT;        int wb = r / KT;
        int tig = lane & 3, gid = lane >> 2;
        int nt = (j < NT) ? j : j - NT;
        int k2 = kt * 8 + ((j < NT) ? 0 : 4) + tig;
        int n  = wb * NT * 8 + nt * 8 + gid;
        unsigned hi, lo;
        split_pack(W[(size_t)(2 * k2) * N + n], W[(size_t)(2 * k2 + 1) * N + n], hi, lo);
        g_Whi[i] = hi;
        g_Wlo[i] = lo;
    }
}

// ---------------------------------------------------------------------------
__global__ void fill_kernel(const float* __restrict__ ew,
                            const int* __restrict__ pid,
                            const int* __restrict__ hid,
                            const float* __restrict__ feat, int nE) {
    int e = blockIdx.x * blockDim.x + threadIdx.x;
    if (e >= nE) return;
    int p = pid[e];
    int h = hid[e];
    float w = ew[e];

    int pos = atomicAdd(&g_cnt_he[h], 1);
    if (pos < HE_CAP) {
        g_list_he[(size_t)h * HE_CAP + pos] = make_float2(__int_as_float(p), w);
    } else {
        const float4* fr = (const float4*)(feat + (size_t)p * D_IN);
        for (int i = 0; i < D_IN / 4; i++) {
            float4 v = fr[i];
            red_add_v4(g_he_feat + (size_t)h * D_IN + i * 4,
                       v.x * w, v.y * w, v.z * w, v.w * w);
        }
    }

    int pos2 = atomicAdd(&g_cnt_p[p], 1);
    if (pos2 < P_CAP) {
        g_list_p[(size_t)p * P_CAP + pos2] = make_float2(__int_as_float(h), w);
    } else {
        int o = atomicAdd(&g_novf, 1);
        if (o < OVF_CAP)
            g_ovf[o] = make_float4(__int_as_float(p), __int_as_float(h), w, 0.f);
    }
}

// ---------------------------------------------------------------------------
__global__ void zero_cluster_kernel() {
    if (g_novf == 0) return;
    int i = blockIdx.x * blockDim.x + threadIdx.x;
    if (i < N_P * (D_IN / 4))
        ((float4*)g_cluster)[i] = make_float4(0.f, 0.f, 0.f, 0.f);
}

// ---------------------------------------------------------------------------
// he_acc v3: 2 independent warps per hyperedge (even/odd edges), each stages
// only its own half-list (no block sync), partials merged via red.global.add
// into the zeroed base (overflow REDs fold in naturally).
// N_HE = 5000 divisible by 4 -> 1250 full blocks.
// ---------------------------------------------------------------------------
__global__ __launch_bounds__(256) void he_acc_kernel() {
    __shared__ float2 s_list[8][HE_CAP / 2];
    int wid = threadIdx.x >> 5, lane = threadIdx.x & 31;
    int he = blockIdx.x * 4 + (wid >> 1);
    int half = wid & 1;

    int n_raw = g_cnt_he[he];
    int n = n_raw < HE_CAP ? n_raw : HE_CAP;
    int nHalf = (n - half + 1) >> 1;   // #edges at indices half, half+2, ...

    for (int i = lane; i < nHalf; i += 32)
        s_list[wid][i] = g_list_he[(size_t)he * HE_CAP + 2 * i + half];
    __syncwarp();

    float4 acc = make_float4(0.f, 0.f, 0.f, 0.f);
    const float4* feat4 = (const float4*)0;  // set below (feat passed via cb)
    // feat pointer passed through constant: use global symbol trick instead
    // (actual feat ptr comes in as kernel arg in launch; see parameter)
    // -- placeholder removed; real code below uses parameter.
    (void)feat4;
    // NOTE: body continues in templated form below.
    // (This kernel is re-declared with the feat parameter.)
}

// real definition with parameter (replaces stub above via different name)
__global__ __launch_bounds__(256) void he_acc3_kernel(const float* __restrict__ feat) {
    __shared__ float2 s_list[8][HE_CAP / 2];
    int wid = threadIdx.x >> 5, lane = threadIdx.x & 31;
    int he = blockIdx.x * 4 + (wid >> 1);
    int half = wid & 1;

    int n_raw = g_cnt_he[he];
    int n = n_raw < HE_CAP ? n_raw : HE_CAP;
    int nHalf = (n - half + 1) >> 1;

    for (int i = lane; i < nHalf; i += 32)
        s_list[wid][i] = g_list_he[(size_t)he * HE_CAP + 2 * i + half];
    __syncwarp();

    float4 acc = make_float4(0.f, 0.f, 0.f, 0.f);
    const float4* feat4 = (const float4*)feat;
    int i = 0;
    for (; i + 4 <= nHalf; i += 4) {
        float2 e0 = s_list[wid][i],     e1 = s_list[wid][i + 1];
        float2 e2 = s_list[wid][i + 2], e3 = s_list[wid][i + 3];
        float4 v0 = feat4[(size_t)__float_as_int(e0.x) * 32 + lane];
        float4 v1 = feat4[(size_t)__float_as_int(e1.x) * 32 + lane];
        float4 v2 = feat4[(size_t)__float_as_int(e2.x) * 32 + lane];
        float4 v3 = feat4[(size_t)__float_as_int(e3.x) * 32 + lane];
        acc.x += e0.y * v0.x; acc.y += e0.y * v0.y; acc.z += e0.y * v0.z; acc.w += e0.y * v0.w;
        acc.x += e1.y * v1.x; acc.y += e1.y * v1.y; acc.z += e1.y * v1.z; acc.w += e1.y * v1.w;
        acc.x += e2.y * v2.x; acc.y += e2.y * v2.y; acc.z += e2.y * v2.z; acc.w += e2.y * v2.w;
        acc.x += e3.y * v3.x; acc.y += e3.y * v3.y; acc.z += e3.y * v3.z; acc.w += e3.y * v3.w;
    }
    for (; i < nHalf; i++) {
        float2 e0 = s_list[wid][i];
        float4 v0 = feat4[(size_t)__float_as_int(e0.x) * 32 + lane];
        acc.x += e0.y * v0.x; acc.y += e0.y * v0.y; acc.z += e0.y * v0.z; acc.w += e0.y * v0.w;
    }
    if (nHalf > 0)
        red_add_v4(g_he_feat + (size_t)he * D_IN + lane * 4, acc.x, acc.y, acc.z, acc.w);
}

// ---------------------------------------------------------------------------
// bf16 MMA machinery; B fragment-packed (LDG.128), A double-buffered LDSM (R11)
// ---------------------------------------------------------------------------
__device__ __forceinline__ void mma_bf16(float (&c)[4], const unsigned (&a)[4],
                                         unsigned b0, unsigned b1) {
    asm volatile(
        "mma.sync.aligned.m16n8k16.row.col.f32.bf16.bf16.f32 "
        "{%0,%1,%2,%3},{%4,%5,%6,%7},{%8,%9},{%0,%1,%2,%3};\n"
        : "+f"(c[0]), "+f"(c[1]), "+f"(c[2]), "+f"(c[3])
        : "r"(a[0]), "r"(a[1]), "r"(a[2]), "r"(a[3]), "r"(b0), "r"(b1));
}

#define LDSM4(R, ADDR) \
    asm volatile("ldmatrix.sync.aligned.m8n8.x4.shared.b16 {%0,%1,%2,%3},[%4];" \
                 : "=r"((R)[0]), "=r"((R)[1]), "=r"((R)[2]), "=r"((R)[3]) : "r"(ADDR))

__device__ __forceinline__ unsigned smem_u32(const void* p) {
    return (unsigned)__cvta_generic_to_shared(p);
}

template <int KT, int NT, int MT>
__device__ __forceinline__ void gemm_bf16(const unsigned (&aAddr)[MT], unsigned loOffBytes,
                                          const uint4* __restrict__ Bhi,
                                          const uint4* __restrict__ Blo,
                                          float (&acc)[MT][NT][4]) {
    constexpr int NB4 = NT / 2;
    unsigned ah0[MT][4], al0[MT][4];
    unsigned bh0[2 * NT], bl0[2 * NT];
#pragma unroll
    for (int mt = 0; mt < MT; mt++) {
        LDSM4(ah0[mt], aAddr[mt]);
        LDSM4(al0[mt], aAddr[mt] + loOffBytes);
    }
#pragma unroll
    for (int q = 0; q < NB4; q++) {
        uint4 vh = __ldg(Bhi + q), vl = __ldg(Blo + q);
        bh0[4 * q + 0] = vh.x; bh0[4 * q + 1] = vh.y; bh0[4 * q + 2] = vh.z; bh0[4 * q + 3] = vh.w;
        bl0[4 * q + 0] = vl.x; bl0[4 * q + 1] = vl.y; bl0[4 * q + 2] = vl.z; bl0[4 * q + 3] = vl.w;
    }
#pragma unroll
    for (int kt = 0; kt < KT; kt++) {
        unsigned ah1[MT][4], al1[MT][4];
        unsigned bh1[2 * NT], bl1[2 * NT];
        if (kt + 1 < KT) {
#pragma unroll
            for (int mt = 0; mt < MT; mt++) {
                LDSM4(ah1[mt], aAddr[mt] + (kt + 1) * 32u);
                LDSM4(al1[mt], aAddr[mt] + loOffBytes + (kt + 1) * 32u);
            }
#pragma unroll
            for (int q = 0; q < NB4; q++) {
                uint4 vh = __ldg(Bhi + (size_t)(kt + 1) * 32 * NB4 + q);
                uint4 vl = __ldg(Blo + (size_t)(kt + 1) * 32 * NB4 + q);
                bh1[4 * q + 0] = vh.x; bh1[4 * q + 1] = vh.y; bh1[4 * q + 2] = vh.z; bh1[4 * q + 3] = vh.w;
                bl1[4 * q + 0] = vl.x; bl1[4 * q + 1] = vl.y; bl1[4 * q + 2] = vl.z; bl1[4 * q + 3] = vl.w;
            }
        }
#pragma unroll
        for (int nt = 0; nt < NT; nt++)
#pragma unroll
            for (int mt = 0; mt < MT; mt++) {
                mma_bf16(acc[mt][nt], al0[mt], bh0[nt], bh0[NT + nt]);
                mma_bf16(acc[mt][nt], ah0[mt], bl0[nt], bl0[NT + nt]);
                mma_bf16(acc[mt][nt], ah0[mt], bh0[nt], bh0[NT + nt]);
            }
#pragma unroll
        for (int mt = 0; mt < MT; mt++)
#pragma unroll
            for (int i = 0; i < 4; i++) { ah0[mt][i] = ah1[mt][i]; al0[mt][i] = al1[mt][i]; }
#pragma unroll
        for (int j = 0; j < 2 * NT; j++) { bh0[j] = bh1[j]; bl0[j] = bl1[j]; }
    }
}

template <int NT, int MT, bool RELU>
__device__ __forceinline__ void epilogue_f32(float* dst, int dstride, int col0,
                                             const float* __restrict__ bias,
                                             float (&acc)[MT][NT][4], int lane) {
    int gid = lane >> 2, tig = lane & 3;
#pragma unroll
    for (int nt = 0; nt < NT; nt++) {
        int c = nt * 8 + tig * 2;
        float bA = __ldg(bias + c), bB = __ldg(bias + c + 1);
#pragma unroll
        for (int mt = 0; mt < MT; mt++) {
            int r = mt * 16 + gid;
            float v0 = acc[mt][nt][0] + bA, v1 = acc[mt][nt][1] + bB;
            float v2 = acc[mt][nt][2] + bA, v3 = acc[mt][nt][3] + bB;
            if (RELU) {
                v0 = fmaxf(v0, 0.f); v1 = fmaxf(v1, 0.f);
                v2 = fmaxf(v2, 0.f); v3 = fmaxf(v3, 0.f);
            }
            dst[(size_t)r * dstride + col0 + c]           = v0;
            dst[(size_t)r * dstride + col0 + c + 1]       = v1;
            dst[(size_t)(r + 8) * dstride + col0 + c]     = v2;
            dst[(size_t)(r + 8) * dstride + col0 + c + 1] = v3;
        }
    }
}

template <int NT, int MT, bool RELU>
__device__ __forceinline__ void epilogue_bf16(unsigned short* hiBase, int strideElems,
                                              int loOffElems, int col0,
                                              const float* __restrict__ bias,
                                              float (&acc)[MT][NT][4], int lane) {
    int gid = lane >> 2, tig = lane & 3;
#pragma unroll
    for (int nt = 0; nt < NT; nt++) {
        int c = nt * 8 + tig * 2;
        float bA = __ldg(bias + c), bB = __ldg(bias + c + 1);
#pragma unroll
        for (int mt = 0; mt < MT; mt++) {
            int r = mt * 16 + gid;
            float v0 = acc[mt][nt][0] + bA, v1 = acc[mt][nt][1] + bB;
            float v2 = acc[mt][nt][2] + bA, v3 = acc[mt][nt][3] + bB;
            if (RELU) {
                v0 = fmaxf(v0, 0.f); v1 = fmaxf(v1, 0.f);
                v2 = fmaxf(v2, 0.f); v3 = fmaxf(v3, 0.f);
            }
            unsigned h01, l01, h23, l23;
            split_pack(v0, v1, h01, l01);
            split_pack(v2, v3, h23, l23);
            int i0 = r * strideElems + col0 + c;
            int i1 = (r + 8) * strideElems + col0 + c;
            *(unsigned*)&hiBase[i0]               = h01;
            *(unsigned*)&hiBase[loOffElems + i0]  = l01;
            *(unsigned*)&hiBase[i1]               = h23;
            *(unsigned*)&hiBase[loOffElems + i1]  = l23;
        }
    }
}

__device__ __forceinline__ void load_tile_planes(unsigned short* plane, int strideElems,
                                                 int loOffElems, const float4* src,
                                                 int row0, int rowMax, int t) {
    for (int i = t; i < 32 * 32; i += 256) {
        int r = i >> 5, c4 = i & 31;
        int gr = row0 + r;
        float4 v = make_float4(0.f, 0.f, 0.f, 0.f);
        if (gr < rowMax) v = src[(size_t)gr * 32 + c4];
        unsigned h01, l01, h23, l23;
        split_pack(v.x, v.y, h01, l01);
        split_pack(v.z, v.w, h23, l23);
        int base = r * strideElems + c4 * 4;
        *(unsigned*)&plane[base]                   = h01;
        *(unsigned*)&plane[base + 2]               = h23;
        *(unsigned*)&plane[loOffElems + base]      = l01;
        *(unsigned*)&plane[loOffElems + base + 2]  = l23;
    }
}

// ---------------------------------------------------------------------------
// attention: 32-row tiles, bf16-split GEMM vs fragment-packed Wh1
// ---------------------------------------------------------------------------
__global__ __launch_bounds__(256) void attn_gemm_kernel(
    const float* __restrict__ bh1, const float* __restrict__ Wh2,
    const float* __restrict__ bh2, const float* __restrict__ Wfuse) {
    __shared__ unsigned short s_he[2 * 32 * PB128];
    __shared__ float s_part[32][8];
    __shared__ float s_attn[32];

    int row0 = blockIdx.x * 32;
    int t = threadIdx.x, wid = t >> 5, lane = t & 31;

    load_tile_planes(s_he, PB128, 32 * PB128, (const float4*)g_he_feat, row0, N_HE, t);
    __syncthreads();

    int m8 = lane >> 3, rIn = lane & 7;
    int rowoff = (m8 & 1) * 8 + rIn;
    int colByte = (m8 >> 1) * 16;
    int gid = lane >> 2, tig = lane & 3;

    int head = wid >> 1;
    int colHalf = (wid & 1) * 32;

    float acc[2][4][4];
#pragma unroll
    for (int a = 0; a < 2; a++)
#pragma unroll
        for (int b = 0; b < 4; b++)
#pragma unroll
            for (int c = 0; c < 4; c++) acc[a][b][c] = 0.f;

    unsigned aAddr[2];
#pragma unroll
    for (int mt = 0; mt < 2; mt++)
        aAddr[mt] = smem_u32(s_he + (mt * 16 + rowoff) * PB128) + colByte;

    size_t fidx = ((size_t)((wid & 1) * 8) * 32 + lane) * 2;
    const uint4* Bhi = (const uint4*)(g_Whi + OFF_WH1 + head * 4096) + fidx;
    const uint4* Blo = (const uint4*)(g_Wlo + OFF_WH1 + head * 4096) + fidx;
    gemm_bf16<8, 4, 2>(aAddr, 32 * PB128 * 2, Bhi, Blo, acc);

    float p0[2] = {0.f, 0.f};
    float p1[2] = {0.f, 0.f};
#pragma unroll
    for (int nt = 0; nt < 4; nt++) {
        int c = head * HEAD_DIM + colHalf + nt * 8 + tig * 2;
        float bA = __ldg(bh1 + c),  bB = __ldg(bh1 + c + 1);
        float wA = __ldg(Wh2 + c),  wB = __ldg(Wh2 + c + 1);
#pragma unroll
        for (int mt = 0; mt < 2; mt++) {
            p0[mt] += fmaxf(acc[mt][nt][0] + bA, 0.f) * wA
                    + fmaxf(acc[mt][nt][1] + bB, 0.f) * wB;
            p1[mt] += fmaxf(acc[mt][nt][2] + bA, 0.f) * wA
                    + fmaxf(acc[mt][nt][3] + bB, 0.f) * wB;
        }
    }
#pragma unroll
    for (int mt = 0; mt < 2; mt++) {
        p0[mt] += __shfl_xor_sync(0xffffffffu, p0[mt], 1);
        p0[mt] += __shfl_xor_sync(0xffffffffu, p0[mt], 2);
        p1[mt] += __shfl_xor_sync(0xffffffffu, p1[mt], 1);
        p1[mt] += __shfl_xor_sync(0xffffffffu, p1[mt], 2);
    }
    if (tig == 0) {
#pragma unroll
        for (int mt = 0; mt < 2; mt++) {
            s_part[mt * 16 + gid][wid]     = p0[mt];
            s_part[mt * 16 + gid + 8][wid] = p1[mt];
        }
    }
    __syncthreads();

    if (t < 32) {
        float a = 0.f;
#pragma unroll
        for (int h = 0; h < N_HEADS; h++) {
            float logit = s_part[t][2 * h] + s_part[t][2 * h + 1] + __ldg(bh2 + h);
            a += __ldg(Wfuse + h) / (1.f + expf(-logit));
        }
        s_attn[t] = a;
    }
    __syncthreads();

    for (int i = t; i < 32 * 32; i += 256) {
        int r = i >> 5, c4 = i & 31;
        int gr = row0 + r;
        if (gr < N_HE) {
            float4 v = ((const float4*)g_he_feat)[(size_t)gr * 32 + c4];
            float a = s_attn[r];
            v.x *= a; v.y *= a; v.z *= a; v.w *= a;
            ((float4*)g_he_w)[(size_t)gr * 32 + c4] = v;
        }
    }
}

// ---------------------------------------------------------------------------
__global__ void ovf_kernel() {
    int novf = g_novf;
    if (novf > OVF_CAP) novf = OVF_CAP;
    int widg = (blockIdx.x * blockDim.x + threadIdx.x) >> 5;
    int lane = threadIdx.x & 31;
    int nw = (gridDim.x * blockDim.x) >> 5;
    for (int e = widg; e < novf; e += nw) {
        float4 o = g_ovf[e];
        int p = __float_as_int(o.x);
        int h = __float_as_int(o.y);
        float w = o.z;
        float4 v = ((const float4*)(g_he_w + (size_t)h * D_IN))[lane];
        red_add_v4(g_cluster + (size_t)p * D_IN + lane * 4,
                   v.x * w, v.y * w, v.z * w, v.w * w);
    }
}

// ---------------------------------------------------------------------------
__global__ __launch_bounds__(256) void p_acc_kernel(int nP) {
    __shared__ float2 s_list[8][P_CAP];
    int wid = threadIdx.x >> 5, lane = threadIdx.x & 31;
    int p = blockIdx.x * 8 + wid;
    if (p >= nP) return;
    int n = g_cnt_p[p];
    if (n > P_CAP) n = P_CAP;
    for (int i = lane; i < n; i += 32) s_list[wid][i] = g_list_p[(size_t)p * P_CAP + i];
    __syncwarp();

    float4 acc = make_float4(0.f, 0.f, 0.f, 0.f);
    if (g_novf > 0)
        acc = ((const float4*)(g_cluster + (size_t)p * D_IN))[lane];

    const float4* hw4 = (const float4*)g_he_w;
    int i = 0;
    for (; i + 4 <= n; i += 4) {
        float2 e0 = s_list[wid][i],     e1 = s_list[wid][i + 1];
        float2 e2 = s_list[wid][i + 2], e3 = s_list[wid][i + 3];
        float4 v0 = hw4[(size_t)__float_as_int(e0.x) * 32 + lane];
        float4 v1 = hw4[(size_t)__float_as_int(e1.x) * 32 + lane];
        float4 v2 = hw4[(size_t)__float_as_int(e2.x) * 32 + lane];
        float4 v3 = hw4[(size_t)__float_as_int(e3.x) * 32 + lane];
        acc.x += e0.y * v0.x; acc.y += e0.y * v0.y; acc.z += e0.y * v0.z; acc.w += e0.y * v0.w;
        acc.x += e1.y * v1.x; acc.y += e1.y * v1.y; acc.z += e1.y * v1.z; acc.w += e1.y * v1.w;
        acc.x += e2.y * v2.x; acc.y += e2.y * v2.y; acc.z += e2.y * v2.z; acc.w += e2.y * v2.w;
        acc.x += e3.y * v3.x; acc.y += e3.y * v3.y; acc.z += e3.y * v3.z; acc.w += e3.y * v3.w;
    }
    for (; i < n; i++) {
        float2 e0 = s_list[wid][i];
        float4 v0 = hw4[(size_t)__float_as_int(e0.x) * 32 + lane];
        acc.x += e0.y * v0.x; acc.y += e0.y * v0.y; acc.z += e0.y * v0.z; acc.w += e0.y * v0.w;
    }
    ((float4*)(g_cluster + (size_t)p * D_IN))[lane] = acc;
}

// ---------------------------------------------------------------------------
// fused MLP, bf16-split, 32 rows/block, fragment-packed B operands (R11 form)
// ---------------------------------------------------------------------------
#define R1OFF 0
#define R2OFF 8704
#define R3OFF 25600
#define GATEOFF 42496
#define LO128 (32 * PB128)
#define LO256 (32 * PB256)

__global__ __launch_bounds__(256, 2) void mlp2_kernel(
    const float* __restrict__ feat,
    const float* __restrict__ bself, const float* __restrict__ bclu,
    const float* __restrict__ bf1,   const float* __restrict__ bf2,
    const float* __restrict__ Wf3,   const float* __restrict__ bf3,
    float* __restrict__ out, int nP) {
    extern __shared__ unsigned short s16[];
    unsigned short* r1 = s16 + R1OFF;
    unsigned short* r2 = s16 + R2OFF;
    unsigned short* r3 = s16 + R3OFF;
    float (*s_gate)[2] = (float (*)[2])(s16 + GATEOFF);
    float* s_x2 = (float*)r2;

    int row0 = blockIdx.x * 32;
    int t = threadIdx.x;
    int wid = t >> 5, lane = t & 31;

    load_tile_planes(r1, PB128, LO128, (const float4*)feat, row0, nP, t);
    load_tile_planes(r2, PB256, LO256, (const float4*)g_cluster, row0, nP, t);
    __syncthreads();

    int m8 = lane >> 3, rIn = lane & 7;
    int rowoff = (m8 & 1) * 8 + rIn;
    int colByte = (m8 >> 1) * 16;
    int gid = lane >> 2, tig = lane & 3;

    // stage A: self_f | clu_f
    {
        float acc[2][4][4];
#pragma unroll
        for (int a = 0; a < 2; a++)
#pragma unroll
            for (int b = 0; b < 4; b++)
#pragma unroll
                for (int c = 0; c < 4; c++) acc[a][b][c] = 0.f;

        unsigned short* aBuf = (wid < 4) ? r1 : r2;
        int aStr             = (wid < 4) ? PB128 : PB256;
        unsigned loOff       = (wid < 4) ? (LO128 * 2) : (LO256 * 2);
        int wOff             = (wid < 4) ? OFF_WSELF : OFF_WCLU;
        const float* bias    = (wid < 4) ? bself : bclu;
        int ncol0            = (wid & 3) * 32;
        int outcol0          = (wid < 4) ? ncol0 : (128 + ncol0);

        unsigned aAddr[2];
#pragma unroll
        for (int mt = 0; mt < 2; mt++)
            aAddr[mt] = smem_u32(aBuf + (mt * 16 + rowoff) * aStr) + colByte;

        size_t fidx = ((size_t)((wid & 3) * 8) * 32 + lane) * 2;
        const uint4* Bhi = (const uint4*)(g_Whi + wOff) + fidx;
        const uint4* Blo = (const uint4*)(g_Wlo + wOff) + fidx;
        gemm_bf16<8, 4, 2>(aAddr, loOff, Bhi, Blo, acc);
        __syncthreads();
        epilogue_bf16<4, 2, false>(r3, PB256, LO256, outcol0, bias + ncol0, acc, lane);
    }
    __syncthreads();

    // stage B: x1 = relu(cat @ Wf1 + bf1)
    {
        float acc[2][4][4];
#pragma unroll
        for (int a = 0; a < 2; a++)
#pragma unroll
            for (int b = 0; b < 4; b++)
#pragma unroll
                for (int c = 0; c < 4; c++) acc[a][b][c] = 0.f;

        int ncol0 = wid * 32;
        unsigned aAddr[2];
#pragma unroll
        for (int mt = 0; mt < 2; mt++)
            aAddr[mt] = smem_u32(r3 + (mt * 16 + rowoff) * PB256) + colByte;
        size_t fidx = ((size_t)(wid * 16) * 32 + lane) * 2;
        const uint4* Bhi = (const uint4*)(g_Whi + OFF_WF1) + fidx;
        const uint4* Blo = (const uint4*)(g_Wlo + OFF_WF1) + fidx;
        gemm_bf16<16, 4, 2>(aAddr, LO256 * 2, Bhi, Blo, acc);
        __syncthreads();
        epilogue_bf16<4, 2, true>(r2, PB256, LO256, ncol0, bf1 + ncol0, acc, lane);
    }
    __syncthreads();

    // stage C: x2 = relu(x1 @ Wf2 + bf2)
    {
        float acc[2][2][4];
#pragma unroll
        for (int a = 0; a < 2; a++)
#pragma unroll
            for (int b = 0; b < 2; b++)
#pragma unroll
                for (int c = 0; c < 4; c++) acc[a][b][c] = 0.f;

        int ncol0 = wid * 16;
        unsigned aAddr[2];
#pragma unroll
        for (int mt = 0; mt < 2; mt++)
            aAddr[mt] = smem_u32(r2 + (mt * 16 + rowoff) * PB256) + colByte;
        size_t fidx = ((size_t)(wid * 16) * 32 + lane) * 1;
        const uint4* Bhi = (const uint4*)(g_Whi + OFF_WF2) + fidx;
        const uint4* Blo = (const uint4*)(g_Wlo + OFF_WF2) + fidx;
        gemm_bf16<16, 2, 2>(aAddr, LO256 * 2, Bhi, Blo, acc);
        __syncthreads();
        epilogue_f32<2, 2, true>(s_x2, 132, ncol0, bf2 + ncol0, acc, lane);
    }
    __syncthreads();

    // stage D: logits + softmax gates
    if (t < 64) {
        int r = t >> 1, l = t & 1;
        float a = __ldg(bf3 + l);
        const float* x = s_x2 + (size_t)r * 132;
#pragma unroll 4
        for (int k = 0; k < 128; k++)
            a += x[k] * __ldg(Wf3 + 2 * k + l);
        s_gate[r][l] = a;
    }
    __syncthreads();
    if (t < 32) {
        float a = s_gate[t][0], b = s_gate[t][1];
        float m = fmaxf(a, b);
        float e0 = expf(a - m), e1 = expf(b - m);
        float inv = 1.f / (e0 + e1);
        s_gate[t][0] = e0 * inv;
        s_gate[t][1] = e1 * inv;
    }
    __syncthreads();

    // stage E
    const float4* feat4 = (const float4*)feat;
    for (int i = t; i < 32 * 32; i += 256) {
        int r = i >> 5, c4 = i & 31;
        int gr = row0 + r;
        if (gr < nP) {
            float4 f = feat4[(size_t)gr * 32 + c4];
            float g0 = s_gate[r][0], g1 = s_gate[r][1];
            int c0 = c4 * 4;
            ushort4 hs = *(const ushort4*)&r3[r * PB256 + c0];
            ushort4 ls = *(const ushort4*)&r3[LO256 + r * PB256 + c0];
            ushort4 hc = *(const ushort4*)&r3[r * PB256 + c0 + 128];
            ushort4 lc = *(const ushort4*)&r3[LO256 + r * PB256 + c0 + 128];
            float4 o;
            o.x = fmaxf((bfu(hs.x) + bfu(ls.x)) * g0 + (bfu(hc.x) + bfu(lc.x)) * g1 + f.x, 0.f);
            o.y = fmaxf((bfu(hs.y) + bfu(ls.y)) * g0 + (bfu(hc.y) + bfu(lc.y)) * g1 + f.y, 0.f);
            o.z = fmaxf((bfu(hs.z) + bfu(ls.z)) * g0 + (bfu(hc.z) + bfu(lc.z)) * g1 + f.z, 0.f);
            o.w = fmaxf((bfu(hs.w) + bfu(ls.w)) * g0 + (bfu(hc.w) + bfu(lc.w)) * g1 + f.w, 0.f);
            ((float4*)out)[(size_t)gr * 32 + c4] = o;
        }
    }
}

// ---------------------------------------------------------------------------
extern "C" void kernel_launch(void* const* d_in, const int* in_sizes, int n_in,
                              void* d_out, int out_size) {
    const float* feat   = (const float*)d_in[0];
    const float* edge_w = (const float*)d_in[1];
    const float* Wself  = (const float*)d_in[2];
    const float* bself  = (const float*)d_in[3];
    const float* Wclu   = (const float*)d_in[4];
    const float* bclu   = (const float*)d_in[5];
    const float* Wh1    = (const float*)d_in[6];
    const float* bh1    = (const float*)d_in[7];
    const float* Wh2    = (const float*)d_in[8];
    const float* bh2    = (const float*)d_in[9];
    const float* Wfuse  = (const float*)d_in[10];
    const float* Wf1    = (const float*)d_in[11];
    const float* bf1    = (const float*)d_in[12];
    const float* Wf2    = (const float*)d_in[13];
    const float* bf2    = (const float*)d_in[14];
    const float* Wf3    = (const float*)d_in[15];
    const float* bf3    = (const float*)d_in[16];
    const int*   e_pid  = (const int*)d_in[17];
    const int*   e_hid  = (const int*)d_in[18];

    int nE = in_sizes[17];
    int nP = in_sizes[0] / D_IN;
    float* out = (float*)d_out;

    int zpN = N_HE * (D_IN / 4);
    zero_pack_kernel<<<(zpN + 255) / 256, 256>>>(Wself, Wclu, Wf1, Wf2, Wh1);

    fill_kernel<<<(nE + 255) / 256, 256>>>(edge_w, e_pid, e_hid, feat, nE);

    zero_cluster_kernel<<<(N_P * (D_IN / 4) + 255) / 256, 256>>>();

    he_acc3_kernel<<<N_HE / 4, 256>>>(feat);

    attn_gemm_kernel<<<(N_HE + 31) / 32, 256>>>(bh1, Wh2, bh2, Wfuse);

    ovf_kernel<<<32, 256>>>();

    p_acc_kernel<<<(nP + 7) / 8, 256>>>(nP);

    size_t smemBytes = (size_t)GATEOFF * 2 + 32 * 2 * sizeof(float);
    cudaFuncSetAttribute(mlp2_kernel, cudaFuncAttributeMaxDynamicSharedMemorySize,
                         (int)smemBytes);
    int nBlocks = (nP + 31) / 32;
    mlp2_kernel<<<nBlocks, 256, smemBytes>>>(feat, bself, bclu, bf1, bf2,
                                             Wf3, bf3, out, nP);
}

// round 14
// speedup vs baseline: 1.0177x; 1.0066x over previous
#include <cuda_runtime.h>
#include <cuda_bf16.h>
#include <math.h>

#define N_P   50000
#define N_HE  5000
#define D_IN  128
#define D_HID 256
#define N_HEADS 4
#define HEAD_DIM 64

#define HE_CAP 256
#define P_CAP  64
#define OVF_CAP 65536

// bf16 plane strides (in bf16 elems): row bytes odd multiple of 16
#define PB128 136
#define PB256 264

// packed-weight sections (u32), fragment-order layout (see pack kernel)
#define OFF_WSELF 0
#define OFF_WCLU  8192
#define OFF_WF1   16384
#define OFF_WF2   49152
#define OFF_WH1   65536
#define PACK_TOTAL 81920

// ---- scratch (no allocation allowed) ----
__device__ float g_he_feat[N_HE * D_IN];
__device__ float g_he_w[N_HE * D_IN];
__device__ float g_cluster[N_P * D_IN];
__device__ int   g_cnt_he[N_HE];
__device__ int   g_cnt_p[N_P];
__device__ float2 g_list_he[N_HE * HE_CAP];
__device__ float2 g_list_p[N_P * P_CAP];
__device__ float4 g_ovf[OVF_CAP];
__device__ int   g_novf;
__device__ __align__(16) unsigned g_Whi[PACK_TOTAL];
__device__ __align__(16) unsigned g_Wlo[PACK_TOTAL];

// ---------------------------------------------------------------------------
__device__ __forceinline__ void red_add_v4(float* dst, float a, float b, float c, float d) {
    asm volatile("red.global.add.v4.f32 [%0], {%1,%2,%3,%4};"
                 :: "l"(dst), "f"(a), "f"(b), "f"(c), "f"(d) : "memory");
}

__device__ __forceinline__ void split_pack(float x0, float x1, unsigned& hi, unsigned& lo) {
    __nv_bfloat16 h0 = __float2bfloat16(x0);
    __nv_bfloat16 h1 = __float2bfloat16(x1);
    __nv_bfloat16 l0 = __float2bfloat16(x0 - __bfloat162float(h0));
    __nv_bfloat16 l1 = __float2bfloat16(x1 - __bfloat162float(h1));
    hi = (unsigned)__bfloat16_as_ushort(h0) | ((unsigned)__bfloat16_as_ushort(h1) << 16);
    lo = (unsigned)__bfloat16_as_ushort(l0) | ((unsigned)__bfloat16_as_ushort(l1) << 16);
}

__device__ __forceinline__ float bfu(unsigned short u) {
    return __bfloat162float(__ushort_as_bfloat16(u));
}

// ---------------------------------------------------------------------------
// zero (he_feat + counters) fused with FRAGMENT-ORDER weight packing
// ---------------------------------------------------------------------------
__global__ void zero_pack_kernel(const float* __restrict__ Wself, const float* __restrict__ Wclu,
                                 const float* __restrict__ Wf1,   const float* __restrict__ Wf2,
                                 const float* __restrict__ Wh1) {
    int i = blockIdx.x * blockDim.x + threadIdx.x;
    if (i < N_HE * (D_IN / 4))
        ((float4*)g_he_feat)[i] = make_float4(0.f, 0.f, 0.f, 0.f);
    if (i < N_HE) g_cnt_he[i] = 0;
    if (i < N_P)  g_cnt_p[i] = 0;
    if (i == 0)   g_novf = 0;
    if (i < PACK_TOTAL) {
        const float* W;
        int N, K, NT, local;
        if (i < OFF_WCLU)      { W = Wself; N = 128; K = 128; NT = 4; local = i; }
        else if (i < OFF_WF1)  { W = Wclu;  N = 128; K = 128; NT = 4; local = i - OFF_WCLU; }
        else if (i < OFF_WF2)  { W = Wf1;   N = 256; K = 256; NT = 4; local = i - OFF_WF1; }
        else if (i < OFF_WH1)  { W = Wf2;   N = 128; K = 256; NT = 2; local = i - OFF_WF2; }
        else {
            local = i - OFF_WH1;
            int head = local / 4096; local -= head * 4096;
            W = Wh1 + (size_t)head * 128 * 64; N = 64; K = 128; NT = 4;
        }
        int KT = K / 16;
        int twoNT = 2 * NT;
        int j = local % twoNT;  int r = local / twoNT;
        int lane = r % 32;      r /= 32;
        int kt = r % KT;        int wb = r / KT;
        int tig = lane & 3, gid = lane >> 2;
        int nt = (j < NT) ? j : j - NT;
        int k2 = kt * 8 + ((j < NT) ? 0 : 4) + tig;
        int n  = wb * NT * 8 + nt * 8 + gid;
        unsigned hi, lo;
        split_pack(W[(size_t)(2 * k2) * N + n], W[(size_t)(2 * k2 + 1) * N + n], hi, lo);
        g_Whi[i] = hi;
        g_Wlo[i] = lo;
    }
}

// ---------------------------------------------------------------------------
__global__ void fill_kernel(const float* __restrict__ ew,
                            const int* __restrict__ pid,
                            const int* __restrict__ hid,
                            const float* __restrict__ feat, int nE) {
    int e = blockIdx.x * blockDim.x + threadIdx.x;
    if (e >= nE) return;
    int p = pid[e];
    int h = hid[e];
    float w = ew[e];

    int pos = atomicAdd(&g_cnt_he[h], 1);
    if (pos < HE_CAP) {
        g_list_he[(size_t)h * HE_CAP + pos] = make_float2(__int_as_float(p), w);
    } else {
        const float4* fr = (const float4*)(feat + (size_t)p * D_IN);
        for (int i = 0; i < D_IN / 4; i++) {
            float4 v = fr[i];
            red_add_v4(g_he_feat + (size_t)h * D_IN + i * 4,
                       v.x * w, v.y * w, v.z * w, v.w * w);
        }
    }

    int pos2 = atomicAdd(&g_cnt_p[p], 1);
    if (pos2 < P_CAP) {
        g_list_p[(size_t)p * P_CAP + pos2] = make_float2(__int_as_float(h), w);
    } else {
        int o = atomicAdd(&g_novf, 1);
        if (o < OVF_CAP)
            g_ovf[o] = make_float4(__int_as_float(p), __int_as_float(h), w, 0.f);
    }
}

// ---------------------------------------------------------------------------
// conditional cluster zero (grid-stride; early-exits when no overflow)
// ---------------------------------------------------------------------------
__global__ void zero_cluster_kernel() {
    if (g_novf == 0) return;
    int stride = gridDim.x * blockDim.x;
    for (int i = blockIdx.x * blockDim.x + threadIdx.x;
         i < N_P * (D_IN / 4); i += stride)
        ((float4*)g_cluster)[i] = make_float4(0.f, 0.f, 0.f, 0.f);
}

// ---------------------------------------------------------------------------
// he_acc: warp per hyperedge (R10 form, measured best), unroll 8 for MLP=8
// ---------------------------------------------------------------------------
__global__ __launch_bounds__(256, 4) void he_acc_kernel(const float* __restrict__ feat) {
    __shared__ float2 s_list[8][HE_CAP];
    int wid = threadIdx.x >> 5, lane = threadIdx.x & 31;
    int he = blockIdx.x * 8 + wid;
    if (he >= N_HE) return;
    int n_raw = g_cnt_he[he];
    int n = n_raw < HE_CAP ? n_raw : HE_CAP;
    for (int i = lane; i < n; i += 32) s_list[wid][i] = g_list_he[(size_t)he * HE_CAP + i];
    __syncwarp();

    float4 acc = make_float4(0.f, 0.f, 0.f, 0.f);
    if (n_raw > HE_CAP)
        acc = ((const float4*)(g_he_feat + (size_t)he * D_IN))[lane];

    const float4* feat4 = (const float4*)feat;
    float4 acc2 = make_float4(0.f, 0.f, 0.f, 0.f);
    int i = 0;
    for (; i + 8 <= n; i += 8) {
        float2 e0 = s_list[wid][i],     e1 = s_list[wid][i + 1];
        float2 e2 = s_list[wid][i + 2], e3 = s_list[wid][i + 3];
        float2 e4 = s_list[wid][i + 4], e5 = s_list[wid][i + 5];
        float2 e6 = s_list[wid][i + 6], e7 = s_list[wid][i + 7];
        float4 v0 = feat4[(size_t)__float_as_int(e0.x) * 32 + lane];
        float4 v1 = feat4[(size_t)__float_as_int(e1.x) * 32 + lane];
        float4 v2 = feat4[(size_t)__float_as_int(e2.x) * 32 + lane];
        float4 v3 = feat4[(size_t)__float_as_int(e3.x) * 32 + lane];
        float4 v4 = feat4[(size_t)__float_as_int(e4.x) * 32 + lane];
        float4 v5 = feat4[(size_t)__float_as_int(e5.x) * 32 + lane];
        float4 v6 = feat4[(size_t)__float_as_int(e6.x) * 32 + lane];
        float4 v7 = feat4[(size_t)__float_as_int(e7.x) * 32 + lane];
        acc.x  += e0.y * v0.x; acc.y  += e0.y * v0.y; acc.z  += e0.y * v0.z; acc.w  += e0.y * v0.w;
        acc2.x += e1.y * v1.x; acc2.y += e1.y * v1.y; acc2.z += e1.y * v1.z; acc2.w += e1.y * v1.w;
        acc.x  += e2.y * v2.x; acc.y  += e2.y * v2.y; acc.z  += e2.y * v2.z; acc.w  += e2.y * v2.w;
        acc2.x += e3.y * v3.x; acc2.y += e3.y * v3.y; acc2.z += e3.y * v3.z; acc2.w += e3.y * v3.w;
        acc.x  += e4.y * v4.x; acc.y  += e4.y * v4.y; acc.z  += e4.y * v4.z; acc.w  += e4.y * v4.w;
        acc2.x += e5.y * v5.x; acc2.y += e5.y * v5.y; acc2.z += e5.y * v5.z; acc2.w += e5.y * v5.w;
        acc.x  += e6.y * v6.x; acc.y  += e6.y * v6.y; acc.z  += e6.y * v6.z; acc.w  += e6.y * v6.w;
        acc2.x += e7.y * v7.x; acc2.y += e7.y * v7.y; acc2.z += e7.y * v7.z; acc2.w += e7.y * v7.w;
    }
    for (; i < n; i++) {
        float2 e0 = s_list[wid][i];
        float4 v0 = feat4[(size_t)__float_as_int(e0.x) * 32 + lane];
        acc.x += e0.y * v0.x; acc.y += e0.y * v0.y; acc.z += e0.y * v0.z; acc.w += e0.y * v0.w;
    }
    acc.x += acc2.x; acc.y += acc2.y; acc.z += acc2.z; acc.w += acc2.w;
    ((float4*)(g_he_feat + (size_t)he * D_IN))[lane] = acc;
}

// ---------------------------------------------------------------------------
// bf16 MMA machinery; B fragment-packed (LDG.128), A double-buffered LDSM
// ---------------------------------------------------------------------------
__device__ __forceinline__ void mma_bf16(float (&c)[4], const unsigned (&a)[4],
                                         unsigned b0, unsigned b1) {
    asm volatile(
        "mma.sync.aligned.m16n8k16.row.col.f32.bf16.bf16.f32 "
        "{%0,%1,%2,%3},{%4,%5,%6,%7},{%8,%9},{%0,%1,%2,%3};\n"
        : "+f"(c[0]), "+f"(c[1]), "+f"(c[2]), "+f"(c[3])
        : "r"(a[0]), "r"(a[1]), "r"(a[2]), "r"(a[3]), "r"(b0), "r"(b1));
}

#define LDSM4(R, ADDR) \
    asm volatile("ldmatrix.sync.aligned.m8n8.x4.shared.b16 {%0,%1,%2,%3},[%4];" \
                 : "=r"((R)[0]), "=r"((R)[1]), "=r"((R)[2]), "=r"((R)[3]) : "r"(ADDR))

__device__ __forceinline__ unsigned smem_u32(const void* p) {
    return (unsigned)__cvta_generic_to_shared(p);
}

template <int KT, int NT, int MT>
__device__ __forceinline__ void gemm_bf16(const unsigned (&aAddr)[MT], unsigned loOffBytes,
                                          const uint4* __restrict__ Bhi,
                                          const uint4* __restrict__ Blo,
                                          float (&acc)[MT][NT][4]) {
    constexpr int NB4 = NT / 2;
    unsigned ah0[MT][4], al0[MT][4];
    unsigned bh0[2 * NT], bl0[2 * NT];
#pragma unroll
    for (int mt = 0; mt < MT; mt++) {
        LDSM4(ah0[mt], aAddr[mt]);
        LDSM4(al0[mt], aAddr[mt] + loOffBytes);
    }
#pragma unroll
    for (int q = 0; q < NB4; q++) {
        uint4 vh = __ldg(Bhi + q), vl = __ldg(Blo + q);
        bh0[4 * q + 0] = vh.x; bh0[4 * q + 1] = vh.y; bh0[4 * q + 2] = vh.z; bh0[4 * q + 3] = vh.w;
        bl0[4 * q + 0] = vl.x; bl0[4 * q + 1] = vl.y; bl0[4 * q + 2] = vl.z; bl0[4 * q + 3] = vl.w;
    }
#pragma unroll
    for (int kt = 0; kt < KT; kt++) {
        unsigned ah1[MT][4], al1[MT][4];
        unsigned bh1[2 * NT], bl1[2 * NT];
        if (kt + 1 < KT) {
#pragma unroll
            for (int mt = 0; mt < MT; mt++) {
                LDSM4(ah1[mt], aAddr[mt] + (kt + 1) * 32u);
                LDSM4(al1[mt], aAddr[mt] + loOffBytes + (kt + 1) * 32u);
            }
#pragma unroll
            for (int q = 0; q < NB4; q++) {
                uint4 vh = __ldg(Bhi + (size_t)(kt + 1) * 32 * NB4 + q);
                uint4 vl = __ldg(Blo + (size_t)(kt + 1) * 32 * NB4 + q);
                bh1[4 * q + 0] = vh.x; bh1[4 * q + 1] = vh.y; bh1[4 * q + 2] = vh.z; bh1[4 * q + 3] = vh.w;
                bl1[4 * q + 0] = vl.x; bl1[4 * q + 1] = vl.y; bl1[4 * q + 2] = vl.z; bl1[4 * q + 3] = vl.w;
            }
        }
#pragma unroll
        for (int nt = 0; nt < NT; nt++)
#pragma unroll
            for (int mt = 0; mt < MT; mt++) {
                mma_bf16(acc[mt][nt], al0[mt], bh0[nt], bh0[NT + nt]);
                mma_bf16(acc[mt][nt], ah0[mt], bl0[nt], bl0[NT + nt]);
                mma_bf16(acc[mt][nt], ah0[mt], bh0[nt], bh0[NT + nt]);
            }
#pragma unroll
        for (int mt = 0; mt < MT; mt++)
#pragma unroll
            for (int i = 0; i < 4; i++) { ah0[mt][i] = ah1[mt][i]; al0[mt][i] = al1[mt][i]; }
#pragma unroll
        for (int j = 0; j < 2 * NT; j++) { bh0[j] = bh1[j]; bl0[j] = bl1[j]; }
    }
}

template <int NT, int MT, bool RELU>
__device__ __forceinline__ void epilogue_f32(float* dst, int dstride, int col0,
                                             const float* __restrict__ bias,
                                             float (&acc)[MT][NT][4], int lane) {
    int gid = lane >> 2, tig = lane & 3;
#pragma unroll
    for (int nt = 0; nt < NT; nt++) {
        int c = nt * 8 + tig * 2;
        float bA = __ldg(bias + c), bB = __ldg(bias + c + 1);
#pragma unroll
        for (int mt = 0; mt < MT; mt++) {
            int r = mt * 16 + gid;
            float v0 = acc[mt][nt][0] + bA, v1 = acc[mt][nt][1] + bB;
            float v2 = acc[mt][nt][2] + bA, v3 = acc[mt][nt][3] + bB;
            if (RELU) {
                v0 = fmaxf(v0, 0.f); v1 = fmaxf(v1, 0.f);
                v2 = fmaxf(v2, 0.f); v3 = fmaxf(v3, 0.f);
            }
            dst[(size_t)r * dstride + col0 + c]           = v0;
            dst[(size_t)r * dstride + col0 + c + 1]       = v1;
            dst[(size_t)(r + 8) * dstride + col0 + c]     = v2;
            dst[(size_t)(r + 8) * dstride + col0 + c + 1] = v3;
        }
    }
}

template <int NT, int MT, bool RELU>
__device__ __forceinline__ void epilogue_bf16(unsigned short* hiBase, int strideElems,
                                              int loOffElems, int col0,
                                              const float* __restrict__ bias,
                                              float (&acc)[MT][NT][4], int lane) {
    int gid = lane >> 2, tig = lane & 3;
#pragma unroll
    for (int nt = 0; nt < NT; nt++) {
        int c = nt * 8 + tig * 2;
        float bA = __ldg(bias + c), bB = __ldg(bias + c + 1);
#pragma unroll
        for (int mt = 0; mt < MT; mt++) {
            int r = mt * 16 + gid;
            float v0 = acc[mt][nt][0] + bA, v1 = acc[mt][nt][1] + bB;
            float v2 = acc[mt][nt][2] + bA, v3 = acc[mt][nt][3] + bB;
            if (RELU) {
                v0 = fmaxf(v0, 0.f); v1 = fmaxf(v1, 0.f);
                v2 = fmaxf(v2, 0.f); v3 = fmaxf(v3, 0.f);
            }
            unsigned h01, l01, h23, l23;
            split_pack(v0, v1, h01, l01);
            split_pack(v2, v3, h23, l23);
            int i0 = r * strideElems + col0 + c;
            int i1 = (r + 8) * strideElems + col0 + c;
            *(unsigned*)&hiBase[i0]               = h01;
            *(unsigned*)&hiBase[loOffElems + i0]  = l01;
            *(unsigned*)&hiBase[i1]               = h23;
            *(unsigned*)&hiBase[loOffElems + i1]  = l23;
        }
    }
}

__device__ __forceinline__ void load_tile_planes(unsigned short* plane, int strideElems,
                                                 int loOffElems, const float4* src,
                                                 int row0, int rowMax, int t) {
    for (int i = t; i < 32 * 32; i += 256) {
        int r = i >> 5, c4 = i & 31;
        int gr = row0 + r;
        float4 v = make_float4(0.f, 0.f, 0.f, 0.f);
        if (gr < rowMax) v = src[(size_t)gr * 32 + c4];
        unsigned h01, l01, h23, l23;
        split_pack(v.x, v.y, h01, l01);
        split_pack(v.z, v.w, h23, l23);
        int base = r * strideElems + c4 * 4;
        *(unsigned*)&plane[base]                   = h01;
        *(unsigned*)&plane[base + 2]               = h23;
        *(unsigned*)&plane[loOffElems + base]      = l01;
        *(unsigned*)&plane[loOffElems + base + 2]  = l23;
    }
}

// ---------------------------------------------------------------------------
// attention: 32-row tiles, bf16-split GEMM vs fragment-packed Wh1
// ---------------------------------------------------------------------------
__global__ __launch_bounds__(256) void attn_gemm_kernel(
    const float* __restrict__ bh1, const float* __restrict__ Wh2,
    const float* __restrict__ bh2, const float* __restrict__ Wfuse) {
    __shared__ unsigned short s_he[2 * 32 * PB128];
    __shared__ float s_part[32][8];
    __shared__ float s_attn[32];

    int row0 = blockIdx.x * 32;
    int t = threadIdx.x, wid = t >> 5, lane = t & 31;

    load_tile_planes(s_he, PB128, 32 * PB128, (const float4*)g_he_feat, row0, N_HE, t);
    __syncthreads();

    int m8 = lane >> 3, rIn = lane & 7;
    int rowoff = (m8 & 1) * 8 + rIn;
    int colByte = (m8 >> 1) * 16;
    int gid = lane >> 2, tig = lane & 3;

    int head = wid >> 1;
    int colHalf = (wid & 1) * 32;

    float acc[2][4][4];
#pragma unroll
    for (int a = 0; a < 2; a++)
#pragma unroll
        for (int b = 0; b < 4; b++)
#pragma unroll
            for (int c = 0; c < 4; c++) acc[a][b][c] = 0.f;

    unsigned aAddr[2];
#pragma unroll
    for (int mt = 0; mt < 2; mt++)
        aAddr[mt] = smem_u32(s_he + (mt * 16 + rowoff) * PB128) + colByte;

    size_t fidx = ((size_t)((wid & 1) * 8) * 32 + lane) * 2;
    const uint4* Bhi = (const uint4*)(g_Whi + OFF_WH1 + head * 4096) + fidx;
    const uint4* Blo = (const uint4*)(g_Wlo + OFF_WH1 + head * 4096) + fidx;
    gemm_bf16<8, 4, 2>(aAddr, 32 * PB128 * 2, Bhi, Blo, acc);

    float p0[2] = {0.f, 0.f};
    float p1[2] = {0.f, 0.f};
#pragma unroll
    for (int nt = 0; nt < 4; nt++) {
        int c = head * HEAD_DIM + colHalf + nt * 8 + tig * 2;
        float bA = __ldg(bh1 + c),  bB = __ldg(bh1 + c + 1);
        float wA = __ldg(Wh2 + c),  wB = __ldg(Wh2 + c + 1);
#pragma unroll
        for (int mt = 0; mt < 2; mt++) {
            p0[mt] += fmaxf(acc[mt][nt][0] + bA, 0.f) * wA
                    + fmaxf(acc[mt][nt][1] + bB, 0.f) * wB;
            p1[mt] += fmaxf(acc[mt][nt][2] + bA, 0.f) * wA
                    + fmaxf(acc[mt][nt][3] + bB, 0.f) * wB;
        }
    }
#pragma unroll
    for (int mt = 0; mt < 2; mt++) {
        p0[mt] += __shfl_xor_sync(0xffffffffu, p0[mt], 1);
        p0[mt] += __shfl_xor_sync(0xffffffffu, p0[mt], 2);
        p1[mt] += __shfl_xor_sync(0xffffffffu, p1[mt], 1);
        p1[mt] += __shfl_xor_sync(0xffffffffu, p1[mt], 2);
    }
    if (tig == 0) {
#pragma unroll
        for (int mt = 0; mt < 2; mt++) {
            s_part[mt * 16 + gid][wid]     = p0[mt];
            s_part[mt * 16 + gid + 8][wid] = p1[mt];
        }
    }
    __syncthreads();

    if (t < 32) {
        float a = 0.f;
#pragma unroll
        for (int h = 0; h < N_HEADS; h++) {
            float logit = s_part[t][2 * h] + s_part[t][2 * h + 1] + __ldg(bh2 + h);
            a += __ldg(Wfuse + h) / (1.f + expf(-logit));
        }
        s_attn[t] = a;
    }
    __syncthreads();

    for (int i = t; i < 32 * 32; i += 256) {
        int r = i >> 5, c4 = i & 31;
        int gr = row0 + r;
        if (gr < N_HE) {
            float4 v = ((const float4*)g_he_feat)[(size_t)gr * 32 + c4];
            float a = s_attn[r];
            v.x *= a; v.y *= a; v.z *= a; v.w *= a;
            ((float4*)g_he_w)[(size_t)gr * 32 + c4] = v;
        }
    }
}

// ---------------------------------------------------------------------------
__global__ void ovf_kernel() {
    int novf = g_novf;
    if (novf > OVF_CAP) novf = OVF_CAP;
    int widg = (blockIdx.x * blockDim.x + threadIdx.x) >> 5;
    int lane = threadIdx.x & 31;
    int nw = (gridDim.x * blockDim.x) >> 5;
    for (int e = widg; e < novf; e += nw) {
        float4 o = g_ovf[e];
        int p = __float_as_int(o.x);
        int h = __float_as_int(o.y);
        float w = o.z;
        float4 v = ((const float4*)(g_he_w + (size_t)h * D_IN))[lane];
        red_add_v4(g_cluster + (size_t)p * D_IN + lane * 4,
                   v.x * w, v.y * w, v.z * w, v.w * w);
    }
}

// ---------------------------------------------------------------------------
__global__ __launch_bounds__(256) void p_acc_kernel(int nP) {
    __shared__ float2 s_list[8][P_CAP];
    int wid = threadIdx.x >> 5, lane = threadIdx.x & 31;
    int p = blockIdx.x * 8 + wid;
    if (p >= nP) return;
    int n = g_cnt_p[p];
    if (n > P_CAP) n = P_CAP;
    for (int i = lane; i < n; i += 32) s_list[wid][i] = g_list_p[(size_t)p * P_CAP + i];
    __syncwarp();

    float4 acc = make_float4(0.f, 0.f, 0.f, 0.f);
    if (g_novf > 0)
        acc = ((const float4*)(g_cluster + (size_t)p * D_IN))[lane];

    const float4* hw4 = (const float4*)g_he_w;
    int i = 0;
    for (; i + 4 <= n; i += 4) {
        float2 e0 = s_list[wid][i],     e1 = s_list[wid][i + 1];
        float2 e2 = s_list[wid][i + 2], e3 = s_list[wid][i + 3];
        float4 v0 = hw4[(size_t)__float_as_int(e0.x) * 32 + lane];
        float4 v1 = hw4[(size_t)__float_as_int(e1.x) * 32 + lane];
        float4 v2 = hw4[(size_t)__float_as_int(e2.x) * 32 + lane];
        float4 v3 = hw4[(size_t)__float_as_int(e3.x) * 32 + lane];
        acc.x += e0.y * v0.x; acc.y += e0.y * v0.y; acc.z += e0.y * v0.z; acc.w += e0.y * v0.w;
        acc.x += e1.y * v1.x; acc.y += e1.y * v1.y; acc.z += e1.y * v1.z; acc.w += e1.y * v1.w;
        acc.x += e2.y * v2.x; acc.y += e2.y * v2.y; acc.z += e2.y * v2.z; acc.w += e2.y * v2.w;
        acc.x += e3.y * v3.x; acc.y += e3.y * v3.y; acc.z += e3.y * v3.z; acc.w += e3.y * v3.w;
    }
    for (; i < n; i++) {
        float2 e0 = s_list[wid][i];
        float4 v0 = hw4[(size_t)__float_as_int(e0.x) * 32 + lane];
        acc.x += e0.y * v0.x; acc.y += e0.y * v0.y; acc.z += e0.y * v0.z; acc.w += e0.y * v0.w;
    }
    ((float4*)(g_cluster + (size_t)p * D_IN))[lane] = acc;
}

// ---------------------------------------------------------------------------
// fused MLP, bf16-split, 32 rows/block, fragment-packed B operands (R11 form)
// ---------------------------------------------------------------------------
#define R1OFF 0
#define R2OFF 8704
#define R3OFF 25600
#define GATEOFF 42496
#define LO128 (32 * PB128)
#define LO256 (32 * PB256)

__global__ __launch_bounds__(256, 2) void mlp2_kernel(
    const float* __restrict__ feat,
    const float* __restrict__ bself, const float* __restrict__ bclu,
    const float* __restrict__ bf1,   const float* __restrict__ bf2,
    const float* __restrict__ Wf3,   const float* __restrict__ bf3,
    float* __restrict__ out, int nP) {
    extern __shared__ unsigned short s16[];
    unsigned short* r1 = s16 + R1OFF;
    unsigned short* r2 = s16 + R2OFF;
    unsigned short* r3 = s16 + R3OFF;
    float (*s_gate)[2] = (float (*)[2])(s16 + GATEOFF);
    float* s_x2 = (float*)r2;

    int row0 = blockIdx.x * 32;
    int t = threadIdx.x;
    int wid = t >> 5, lane = t & 31;

    load_tile_planes(r1, PB128, LO128, (const float4*)feat, row0, nP, t);
    load_tile_planes(r2, PB256, LO256, (const float4*)g_cluster, row0, nP, t);
    __syncthreads();

    int m8 = lane >> 3, rIn = lane & 7;
    int rowoff = (m8 & 1) * 8 + rIn;
    int colByte = (m8 >> 1) * 16;
    int gid = lane >> 2, tig = lane & 3;

    // stage A: self_f | clu_f
    {
        float acc[2][4][4];
#pragma unroll
        for (int a = 0; a < 2; a++)
#pragma unroll
            for (int b = 0; b < 4; b++)
#pragma unroll
                for (int c = 0; c < 4; c++) acc[a][b][c] = 0.f;

        unsigned short* aBuf = (wid < 4) ? r1 : r2;
        int aStr             = (wid < 4) ? PB128 : PB256;
        unsigned loOff       = (wid < 4) ? (LO128 * 2) : (LO256 * 2);
        int wOff             = (wid < 4) ? OFF_WSELF : OFF_WCLU;
        const float* bias    = (wid < 4) ? bself : bclu;
        int ncol0            = (wid & 3) * 32;
        int outcol0          = (wid < 4) ? ncol0 : (128 + ncol0);

        unsigned aAddr[2];
#pragma unroll
        for (int mt = 0; mt < 2; mt++)
            aAddr[mt] = smem_u32(aBuf + (mt * 16 + rowoff) * aStr) + colByte;

        size_t fidx = ((size_t)((wid & 3) * 8) * 32 + lane) * 2;
        const uint4* Bhi = (const uint4*)(g_Whi + wOff) + fidx;
        const uint4* Blo = (const uint4*)(g_Wlo + wOff) + fidx;
        gemm_bf16<8, 4, 2>(aAddr, loOff, Bhi, Blo, acc);
        __syncthreads();
        epilogue_bf16<4, 2, false>(r3, PB256, LO256, outcol0, bias + ncol0, acc, lane);
    }
    __syncthreads();

    // stage B: x1 = relu(cat @ Wf1 + bf1)
    {
        float acc[2][4][4];
#pragma unroll
        for (int a = 0; a < 2; a++)
#pragma unroll
            for (int b = 0; b < 4; b++)
#pragma unroll
                for (int c = 0; c < 4; c++) acc[a][b][c] = 0.f;

        int ncol0 = wid * 32;
        unsigned aAddr[2];
#pragma unroll
        for (int mt = 0; mt < 2; mt++)
            aAddr[mt] = smem_u32(r3 + (mt * 16 + rowoff) * PB256) + colByte;
        size_t fidx = ((size_t)(wid * 16) * 32 + lane) * 2;
        const uint4* Bhi = (const uint4*)(g_Whi + OFF_WF1) + fidx;
        const uint4* Blo = (const uint4*)(g_Wlo + OFF_WF1) + fidx;
        gemm_bf16<16, 4, 2>(aAddr, LO256 * 2, Bhi, Blo, acc);
        __syncthreads();
        epilogue_bf16<4, 2, true>(r2, PB256, LO256, ncol0, bf1 + ncol0, acc, lane);
    }
    __syncthreads();

    // stage C: x2 = relu(x1 @ Wf2 + bf2)
    {
        float acc[2][2][4];
#pragma unroll
        for (int a = 0; a < 2; a++)
#pragma unroll
            for (int b = 0; b < 2; b++)
#pragma unroll
                for (int c = 0; c < 4; c++) acc[a][b][c] = 0.f;

        int ncol0 = wid * 16;
        unsigned aAddr[2];
#pragma unroll
        for (int mt = 0; mt < 2; mt++)
            aAddr[mt] = smem_u32(r2 + (mt * 16 + rowoff) * PB256) + colByte;
        size_t fidx = ((size_t)(wid * 16) * 32 + lane) * 1;
        const uint4* Bhi = (const uint4*)(g_Whi + OFF_WF2) + fidx;
        const uint4* Blo = (const uint4*)(g_Wlo + OFF_WF2) + fidx;
        gemm_bf16<16, 2, 2>(aAddr, LO256 * 2, Bhi, Blo, acc);
        __syncthreads();
        epilogue_f32<2, 2, true>(s_x2, 132, ncol0, bf2 + ncol0, acc, lane);
    }
    __syncthreads();

    // stage D: logits + softmax gates
    if (t < 64) {
        int r = t >> 1, l = t & 1;
        float a = __ldg(bf3 + l);
        const float* x = s_x2 + (size_t)r * 132;
#pragma unroll 4
        for (int k = 0; k < 128; k++)
            a += x[k] * __ldg(Wf3 + 2 * k + l);
        s_gate[r][l] = a;
    }
    __syncthreads();
    if (t < 32) {
        float a = s_gate[t][0], b = s_gate[t][1];
        float m = fmaxf(a, b);
        float e0 = expf(a - m), e1 = expf(b - m);
        float inv = 1.f / (e0 + e1);
        s_gate[t][0] = e0 * inv;
        s_gate[t][1] = e1 * inv;
    }
    __syncthreads();

    // stage E
    const float4* feat4 = (const float4*)feat;
    for (int i = t; i < 32 * 32; i += 256) {
        int r = i >> 5, c4 = i & 31;
        int gr = row0 + r;
        if (gr < nP) {
            float4 f = feat4[(size_t)gr * 32 + c4];
            float g0 = s_gate[r][0], g1 = s_gate[r][1];
            int c0 = c4 * 4;
            ushort4 hs = *(const ushort4*)&r3[r * PB256 + c0];
            ushort4 ls = *(const ushort4*)&r3[LO256 + r * PB256 + c0];
            ushort4 hc = *(const ushort4*)&r3[r * PB256 + c0 + 128];
            ushort4 lc = *(const ushort4*)&r3[LO256 + r * PB256 + c0 + 128];
            float4 o;
            o.x = fmaxf((bfu(hs.x) + bfu(ls.x)) * g0 + (bfu(hc.x) + bfu(lc.x)) * g1 + f.x, 0.f);
            o.y = fmaxf((bfu(hs.y) + bfu(ls.y)) * g0 + (bfu(hc.y) + bfu(lc.y)) * g1 + f.y, 0.f);
            o.z = fmaxf((bfu(hs.z) + bfu(ls.z)) * g0 + (bfu(hc.z) + bfu(lc.z)) * g1 + f.z, 0.f);
            o.w = fmaxf((bfu(hs.w) + bfu(ls.w)) * g0 + (bfu(hc.w) + bfu(lc.w)) * g1 + f.w, 0.f);
            ((float4*)out)[(size_t)gr * 32 + c4] = o;
        }
    }
}

// ---------------------------------------------------------------------------
extern "C" void kernel_launch(void* const* d_in, const int* in_sizes, int n_in,
                              void* d_out, int out_size) {
    const float* feat   = (const float*)d_in[0];
    const float* edge_w = (const float*)d_in[1];
    const float* Wself  = (const float*)d_in[2];
    const float* bself  = (const float*)d_in[3];
    const float* Wclu   = (const float*)d_in[4];
    const float* bclu   = (const float*)d_in[5];
    const float* Wh1    = (const float*)d_in[6];
    const float* bh1    = (const float*)d_in[7];
    const float* Wh2    = (const float*)d_in[8];
    const float* bh2    = (const float*)d_in[9];
    const float* Wfuse  = (const float*)d_in[10];
    const float* Wf1    = (const float*)d_in[11];
    const float* bf1    = (const float*)d_in[12];
    const float* Wf2    = (const float*)d_in[13];
    const float* bf2    = (const float*)d_in[14];
    const float* Wf3    = (const float*)d_in[15];
    const float* bf3    = (const float*)d_in[16];
    const int*   e_pid  = (const int*)d_in[17];
    const int*   e_hid  = (const int*)d_in[18];

    int nE = in_sizes[17];
    int nP = in_sizes[0] / D_IN;
    float* out = (float*)d_out;

    int zpN = N_HE * (D_IN / 4);
    zero_pack_kernel<<<(zpN + 255) / 256, 256>>>(Wself, Wclu, Wf1, Wf2, Wh1);

    fill_kernel<<<(nE + 255) / 256, 256>>>(edge_w, e_pid, e_hid, feat, nE);

    zero_cluster_kernel<<<592, 256>>>();

    he_acc_kernel<<<(N_HE + 7) / 8, 256>>>(feat);

    attn_gemm_kernel<<<(N_HE + 31) / 32, 256>>>(bh1, Wh2, bh2, Wfuse);

    ovf_kernel<<<32, 256>>>();

    p_acc_kernel<<<(nP + 7) / 8, 256>>>(nP);

    size_t smemBytes = (size_t)GATEOFF * 2 + 32 * 2 * sizeof(float);
    cudaFuncSetAttribute(mlp2_kernel, cudaFuncAttributeMaxDynamicSharedMemorySize,
                         (int)smemBytes);
    int nBlocks = (nP + 31) / 32;
    mlp2_kernel<<<nBlocks, 256, smemBytes>>>(feat, bself, bclu, bf1, bf2,
                                             Wf3, bf3, out, nP);
}

// round 16
// speedup vs baseline: 1.0428x; 1.0247x over previous
#include <cuda_runtime.h>
#include <cuda_bf16.h>
#include <math.h>

#define N_P   50000
#define N_HE  5000
#define D_IN  128
#define D_HID 256
#define N_HEADS 4
#define HEAD_DIM 64

#define HE_CAP 256
#define P_CAP  64
#define OVF_CAP 65536

// bf16 plane strides (in bf16 elems): row bytes odd multiple of 16
#define PB128 136
#define PB256 264

// packed-weight sections (u32), fragment-order layout (see pack kernel)
#define OFF_WSELF 0
#define OFF_WCLU  8192
#define OFF_WF1   16384
#define OFF_WF2   49152
#define OFF_WH1   65536
#define PACK_TOTAL 81920

// ---- scratch (no allocation allowed) ----
__device__ float g_he_feat[N_HE * D_IN];
__device__ float g_he_w[N_HE * D_IN];
__device__ float g_cluster[N_P * D_IN];
__device__ int   g_cnt_he[N_HE];
__device__ int   g_cnt_p[N_P];
__device__ float2 g_list_he[N_HE * HE_CAP];
__device__ float2 g_list_p[N_P * P_CAP];
__device__ float4 g_ovf[OVF_CAP];
__device__ int   g_novf;
__device__ __align__(16) unsigned g_Whi[PACK_TOTAL];
__device__ __align__(16) unsigned g_Wlo[PACK_TOTAL];

// ---------------------------------------------------------------------------
__device__ __forceinline__ void red_add_v4(float* dst, float a, float b, float c, float d) {
    asm volatile("red.global.add.v4.f32 [%0], {%1,%2,%3,%4};"
                 :: "l"(dst), "f"(a), "f"(b), "f"(c), "f"(d) : "memory");
}

__device__ __forceinline__ void split_pack(float x0, float x1, unsigned& hi, unsigned& lo) {
    __nv_bfloat16 h0 = __float2bfloat16(x0);
    __nv_bfloat16 h1 = __float2bfloat16(x1);
    __nv_bfloat16 l0 = __float2bfloat16(x0 - __bfloat162float(h0));
    __nv_bfloat16 l1 = __float2bfloat16(x1 - __bfloat162float(h1));
    hi = (unsigned)__bfloat16_as_ushort(h0) | ((unsigned)__bfloat16_as_ushort(h1) << 16);
    lo = (unsigned)__bfloat16_as_ushort(l0) | ((unsigned)__bfloat16_as_ushort(l1) << 16);
}

__device__ __forceinline__ float bfu(unsigned short u) {
    return __bfloat162float(__ushort_as_bfloat16(u));
}

// ---------------------------------------------------------------------------
// zero (he_feat + counters) fused with FRAGMENT-ORDER weight packing
// ---------------------------------------------------------------------------
__global__ void zero_pack_kernel(const float* __restrict__ Wself, const float* __restrict__ Wclu,
                                 const float* __restrict__ Wf1,   const float* __restrict__ Wf2,
                                 const float* __restrict__ Wh1) {
    int i = blockIdx.x * blockDim.x + threadIdx.x;
    if (i < N_HE * (D_IN / 4))
        ((float4*)g_he_feat)[i] = make_float4(0.f, 0.f, 0.f, 0.f);
    if (i < N_HE) g_cnt_he[i] = 0;
    if (i < N_P)  g_cnt_p[i] = 0;
    if (i == 0)   g_novf = 0;
    if (i < PACK_TOTAL) {
        const float* W;
        int N, K, NT, local;
        if (i < OFF_WCLU)      { W = Wself; N = 128; K = 128; NT = 4; local = i; }
        else if (i < OFF_WF1)  { W = Wclu;  N = 128; K = 128; NT = 4; local = i - OFF_WCLU; }
        else if (i < OFF_WF2)  { W = Wf1;   N = 256; K = 256; NT = 4; local = i - OFF_WF1; }
        else if (i < OFF_WH1)  { W = Wf2;   N = 128; K = 256; NT = 2; local = i - OFF_WF2; }
        else {
            local = i - OFF_WH1;
            int head = local / 4096; local -= head * 4096;
            W = Wh1 + (size_t)head * 128 * 64; N = 64; K = 128; NT = 4;
        }
        int KT = K / 16;
        int twoNT = 2 * NT;
        int j = local % twoNT;  int r = local / twoNT;
        int lane = r % 32;      r /= 32;
        int kt = r % KT;        int wb = r / KT;
        int tig = lane & 3, gid = lane >> 2;
        int nt = (j < NT) ? j : j - NT;
        int k2 = kt * 8 + ((j < NT) ? 0 : 4) + tig;
        int n  = wb * NT * 8 + nt * 8 + gid;
        unsigned hi, lo;
        split_pack(W[(size_t)(2 * k2) * N + n], W[(size_t)(2 * k2 + 1) * N + n], hi, lo);
        g_Whi[i] = hi;
        g_Wlo[i] = lo;
    }
}

// ---------------------------------------------------------------------------
__global__ void fill_kernel(const float* __restrict__ ew,
                            const int* __restrict__ pid,
                            const int* __restrict__ hid,
                            const float* __restrict__ feat, int nE) {
    int e = blockIdx.x * blockDim.x + threadIdx.x;
    if (e >= nE) return;
    int p = pid[e];
    int h = hid[e];
    float w = ew[e];

    int pos = atomicAdd(&g_cnt_he[h], 1);
    if (pos < HE_CAP) {
        g_list_he[(size_t)h * HE_CAP + pos] = make_float2(__int_as_float(p), w);
    } else {
        const float4* fr = (const float4*)(feat + (size_t)p * D_IN);
        for (int i = 0; i < D_IN / 4; i++) {
            float4 v = fr[i];
            red_add_v4(g_he_feat + (size_t)h * D_IN + i * 4,
                       v.x * w, v.y * w, v.z * w, v.w * w);
        }
    }

    int pos2 = atomicAdd(&g_cnt_p[p], 1);
    if (pos2 < P_CAP) {
        g_list_p[(size_t)p * P_CAP + pos2] = make_float2(__int_as_float(h), w);
    } else {
        int o = atomicAdd(&g_novf, 1);
        if (o < OVF_CAP)
            g_ovf[o] = make_float4(__int_as_float(p), __int_as_float(h), w, 0.f);
    }
}

// ---------------------------------------------------------------------------
// conditional cluster zero (grid-stride; early-exits when no overflow)
// ---------------------------------------------------------------------------
__global__ void zero_cluster_kernel() {
    if (g_novf == 0) return;
    int stride = gridDim.x * blockDim.x;
    for (int i = blockIdx.x * blockDim.x + threadIdx.x;
         i < N_P * (D_IN / 4); i += stride)
        ((float4*)g_cluster)[i] = make_float4(0.f, 0.f, 0.f, 0.f);
}

// ---------------------------------------------------------------------------
// he_acc: warp per hyperedge, unroll 4 (R10/R12 measured-best form, 29.4us)
// ---------------------------------------------------------------------------
__global__ __launch_bounds__(256) void he_acc_kernel(const float* __restrict__ feat) {
    __shared__ float2 s_list[8][HE_CAP];
    int wid = threadIdx.x >> 5, lane = threadIdx.x & 31;
    int he = blockIdx.x * 8 + wid;
    if (he >= N_HE) return;
    int n_raw = g_cnt_he[he];
    int n = n_raw < HE_CAP ? n_raw : HE_CAP;
    for (int i = lane; i < n; i += 32) s_list[wid][i] = g_list_he[(size_t)he * HE_CAP + i];
    __syncwarp();

    float4 acc = make_float4(0.f, 0.f, 0.f, 0.f);
    if (n_raw > HE_CAP)
        acc = ((const float4*)(g_he_feat + (size_t)he * D_IN))[lane];

    const float4* feat4 = (const float4*)feat;
    int i = 0;
    for (; i + 4 <= n; i += 4) {
        float2 e0 = s_list[wid][i],     e1 = s_list[wid][i + 1];
        float2 e2 = s_list[wid][i + 2], e3 = s_list[wid][i + 3];
        float4 v0 = feat4[(size_t)__float_as_int(e0.x) * 32 + lane];
        float4 v1 = feat4[(size_t)__float_as_int(e1.x) * 32 + lane];
        float4 v2 = feat4[(size_t)__float_as_int(e2.x) * 32 + lane];
        float4 v3 = feat4[(size_t)__float_as_int(e3.x) * 32 + lane];
        acc.x += e0.y * v0.x; acc.y += e0.y * v0.y; acc.z += e0.y * v0.z; acc.w += e0.y * v0.w;
        acc.x += e1.y * v1.x; acc.y += e1.y * v1.y; acc.z += e1.y * v1.z; acc.w += e1.y * v1.w;
        acc.x += e2.y * v2.x; acc.y += e2.y * v2.y; acc.z += e2.y * v2.z; acc.w += e2.y * v2.w;
        acc.x += e3.y * v3.x; acc.y += e3.y * v3.y; acc.z += e3.y * v3.z; acc.w += e3.y * v3.w;
    }
    for (; i < n; i++) {
        float2 e0 = s_list[wid][i];
        float4 v0 = feat4[(size_t)__float_as_int(e0.x) * 32 + lane];
        acc.x += e0.y * v0.x; acc.y += e0.y * v0.y; acc.z += e0.y * v0.z; acc.w += e0.y * v0.w;
    }
    ((float4*)(g_he_feat + (size_t)he * D_IN))[lane] = acc;
}

// ---------------------------------------------------------------------------
// bf16 MMA machinery; B fragment-packed (LDG.128), A double-buffered LDSM
// ---------------------------------------------------------------------------
__device__ __forceinline__ void mma_bf16(float (&c)[4], const unsigned (&a)[4],
                                         unsigned b0, unsigned b1) {
    asm volatile(
        "mma.sync.aligned.m16n8k16.row.col.f32.bf16.bf16.f32 "
        "{%0,%1,%2,%3},{%4,%5,%6,%7},{%8,%9},{%0,%1,%2,%3};\n"
        : "+f"(c[0]), "+f"(c[1]), "+f"(c[2]), "+f"(c[3])
        : "r"(a[0]), "r"(a[1]), "r"(a[2]), "r"(a[3]), "r"(b0), "r"(b1));
}

#define LDSM4(R, ADDR) \
    asm volatile("ldmatrix.sync.aligned.m8n8.x4.shared.b16 {%0,%1,%2,%3},[%4];" \
                 : "=r"((R)[0]), "=r"((R)[1]), "=r"((R)[2]), "=r"((R)[3]) : "r"(ADDR))

__device__ __forceinline__ unsigned smem_u32(const void* p) {
    return (unsigned)__cvta_generic_to_shared(p);
}

template <int KT, int NT, int MT>
__device__ __forceinline__ void gemm_bf16(const unsigned (&aAddr)[MT], unsigned loOffBytes,
                                          const uint4* __restrict__ Bhi,
                                          const uint4* __restrict__ Blo,
                                          float (&acc)[MT][NT][4]) {
    constexpr int NB4 = NT / 2;
    unsigned ah0[MT][4], al0[MT][4];
    unsigned bh0[2 * NT], bl0[2 * NT];
#pragma unroll
    for (int mt = 0; mt < MT; mt++) {
        LDSM4(ah0[mt], aAddr[mt]);
        LDSM4(al0[mt], aAddr[mt] + loOffBytes);
    }
#pragma unroll
    for (int q = 0; q < NB4; q++) {
        uint4 vh = __ldg(Bhi + q), vl = __ldg(Blo + q);
        bh0[4 * q + 0] = vh.x; bh0[4 * q + 1] = vh.y; bh0[4 * q + 2] = vh.z; bh0[4 * q + 3] = vh.w;
        bl0[4 * q + 0] = vl.x; bl0[4 * q + 1] = vl.y; bl0[4 * q + 2] = vl.z; bl0[4 * q + 3] = vl.w;
    }
#pragma unroll
    for (int kt = 0; kt < KT; kt++) {
        unsigned ah1[MT][4], al1[MT][4];
        unsigned bh1[2 * NT], bl1[2 * NT];
        if (kt + 1 < KT) {
#pragma unroll
            for (int mt = 0; mt < MT; mt++) {
                LDSM4(ah1[mt], aAddr[mt] + (kt + 1) * 32u);
                LDSM4(al1[mt], aAddr[mt] + loOffBytes + (kt + 1) * 32u);
            }
#pragma unroll
            for (int q = 0; q < NB4; q++) {
                uint4 vh = __ldg(Bhi + (size_t)(kt + 1) * 32 * NB4 + q);
                uint4 vl = __ldg(Blo + (size_t)(kt + 1) * 32 * NB4 + q);
                bh1[4 * q + 0] = vh.x; bh1[4 * q + 1] = vh.y; bh1[4 * q + 2] = vh.z; bh1[4 * q + 3] = vh.w;
                bl1[4 * q + 0] = vl.x; bl1[4 * q + 1] = vl.y; bl1[4 * q + 2] = vl.z; bl1[4 * q + 3] = vl.w;
            }
        }
#pragma unroll
        for (int nt = 0; nt < NT; nt++)
#pragma unroll
            for (int mt = 0; mt < MT; mt++) {
                mma_bf16(acc[mt][nt], al0[mt], bh0[nt], bh0[NT + nt]);
                mma_bf16(acc[mt][nt], ah0[mt], bl0[nt], bl0[NT + nt]);
                mma_bf16(acc[mt][nt], ah0[mt], bh0[nt], bh0[NT + nt]);
            }
#pragma unroll
        for (int mt = 0; mt < MT; mt++)
#pragma unroll
            for (int i = 0; i < 4; i++) { ah0[mt][i] = ah1[mt][i]; al0[mt][i] = al1[mt][i]; }
#pragma unroll
        for (int j = 0; j < 2 * NT; j++) { bh0[j] = bh1[j]; bl0[j] = bl1[j]; }
    }
}

template <int NT, int MT, bool RELU>
__device__ __forceinline__ void epilogue_f32(float* dst, int dstride, int col0,
                                             const float* __restrict__ bias,
                                             float (&acc)[MT][NT][4], int lane) {
    int gid = lane >> 2, tig = lane & 3;
#pragma unroll
    for (int nt = 0; nt < NT; nt++) {
        int c = nt * 8 + tig * 2;
        float bA = __ldg(bias + c), bB = __ldg(bias + c + 1);
#pragma unroll
        for (int mt = 0; mt < MT; mt++) {
            int r = mt * 16 + gid;
            float v0 = acc[mt][nt][0] + bA, v1 = acc[mt][nt][1] + bB;
            float v2 = acc[mt][nt][2] + bA, v3 = acc[mt][nt][3] + bB;
            if (RELU) {
                v0 = fmaxf(v0, 0.f); v1 = fmaxf(v1, 0.f);
                v2 = fmaxf(v2, 0.f); v3 = fmaxf(v3, 0.f);
            }
            dst[(size_t)r * dstride + col0 + c]           = v0;
            dst[(size_t)r * dstride + col0 + c + 1]       = v1;
            dst[(size_t)(r + 8) * dstride + col0 + c]     = v2;
            dst[(size_t)(r + 8) * dstride + col0 + c + 1] = v3;
        }
    }
}

template <int NT, int MT, bool RELU>
__device__ __forceinline__ void epilogue_bf16(unsigned short* hiBase, int strideElems,
                                              int loOffElems, int col0,
                                              const float* __restrict__ bias,
                                              float (&acc)[MT][NT][4], int lane) {
    int gid = lane >> 2, tig = lane & 3;
#pragma unroll
    for (int nt = 0; nt < NT; nt++) {
        int c = nt * 8 + tig * 2;
        float bA = __ldg(bias + c), bB = __ldg(bias + c + 1);
#pragma unroll
        for (int mt = 0; mt < MT; mt++) {
            int r = mt * 16 + gid;
            float v0 = acc[mt][nt][0] + bA, v1 = acc[mt][nt][1] + bB;
            float v2 = acc[mt][nt][2] + bA, v3 = acc[mt][nt][3] + bB;
            if (RELU) {
                v0 = fmaxf(v0, 0.f); v1 = fmaxf(v1, 0.f);
                v2 = fmaxf(v2, 0.f); v3 = fmaxf(v3, 0.f);
            }
            unsigned h01, l01, h23, l23;
            split_pack(v0, v1, h01, l01);
            split_pack(v2, v3, h23, l23);
            int i0 = r * strideElems + col0 + c;
            int i1 = (r + 8) * strideElems + col0 + c;
            *(unsigned*)&hiBase[i0]               = h01;
            *(unsigned*)&hiBase[loOffElems + i0]  = l01;
            *(unsigned*)&hiBase[i1]               = h23;
            *(unsigned*)&hiBase[loOffElems + i1]  = l23;
        }
    }
}

__device__ __forceinline__ void load_tile_planes(unsigned short* plane, int strideElems,
                                                 int loOffElems, const float4* src,
                                                 int row0, int rowMax, int t) {
    for (int i = t; i < 32 * 32; i += 256) {
        int r = i >> 5, c4 = i & 31;
        int gr = row0 + r;
        float4 v = make_float4(0.f, 0.f, 0.f, 0.f);
        if (gr < rowMax) v = src[(size_t)gr * 32 + c4];
        unsigned h01, l01, h23, l23;
        split_pack(v.x, v.y, h01, l01);
        split_pack(v.z, v.w, h23, l23);
        int base = r * strideElems + c4 * 4;
        *(unsigned*)&plane[base]                   = h01;
        *(unsigned*)&plane[base + 2]               = h23;
        *(unsigned*)&plane[loOffElems + base]      = l01;
        *(unsigned*)&plane[loOffElems + base + 2]  = l23;
    }
}

// ---------------------------------------------------------------------------
// attention: 32-row tiles, bf16-split GEMM vs fragment-packed Wh1
// ---------------------------------------------------------------------------
__global__ __launch_bounds__(256) void attn_gemm_kernel(
    const float* __restrict__ bh1, const float* __restrict__ Wh2,
    const float* __restrict__ bh2, const float* __restrict__ Wfuse) {
    __shared__ unsigned short s_he[2 * 32 * PB128];
    __shared__ float s_part[32][8];
    __shared__ float s_attn[32];

    int row0 = blockIdx.x * 32;
    int t = threadIdx.x, wid = t >> 5, lane = t & 31;

    load_tile_planes(s_he, PB128, 32 * PB128, (const float4*)g_he_feat, row0, N_HE, t);
    __syncthreads();

    int m8 = lane >> 3, rIn = lane & 7;
    int rowoff = (m8 & 1) * 8 + rIn;
    int colByte = (m8 >> 1) * 16;
    int gid = lane >> 2, tig = lane & 3;

    int head = wid >> 1;
    int colHalf = (wid & 1) * 32;

    float acc[2][4][4];
#pragma unroll
    for (int a = 0; a < 2; a++)
#pragma unroll
        for (int b = 0; b < 4; b++)
#pragma unroll
            for (int c = 0; c < 4; c++) acc[a][b][c] = 0.f;

    unsigned aAddr[2];
#pragma unroll
    for (int mt = 0; mt < 2; mt++)
        aAddr[mt] = smem_u32(s_he + (mt * 16 + rowoff) * PB128) + colByte;

    size_t fidx = ((size_t)((wid & 1) * 8) * 32 + lane) * 2;
    const uint4* Bhi = (const uint4*)(g_Whi + OFF_WH1 + head * 4096) + fidx;
    const uint4* Blo = (const uint4*)(g_Wlo + OFF_WH1 + head * 4096) + fidx;
    gemm_bf16<8, 4, 2>(aAddr, 32 * PB128 * 2, Bhi, Blo, acc);

    float p0[2] = {0.f, 0.f};
    float p1[2] = {0.f, 0.f};
#pragma unroll
    for (int nt = 0; nt < 4; nt++) {
        int c = head * HEAD_DIM + colHalf + nt * 8 + tig * 2;
        float bA = __ldg(bh1 + c),  bB = __ldg(bh1 + c + 1);
        float wA = __ldg(Wh2 + c),  wB = __ldg(Wh2 + c + 1);
#pragma unroll
        for (int mt = 0; mt < 2; mt++) {
            p0[mt] += fmaxf(acc[mt][nt][0] + bA, 0.f) * wA
                    + fmaxf(acc[mt][nt][1] + bB, 0.f) * wB;
            p1[mt] += fmaxf(acc[mt][nt][2] + bA, 0.f) * wA
                    + fmaxf(acc[mt][nt][3] + bB, 0.f) * wB;
        }
    }
#pragma unroll
    for (int mt = 0; mt < 2; mt++) {
        p0[mt] += __shfl_xor_sync(0xffffffffu, p0[mt], 1);
        p0[mt] += __shfl_xor_sync(0xffffffffu, p0[mt], 2);
        p1[mt] += __shfl_xor_sync(0xffffffffu, p1[mt], 1);
        p1[mt] += __shfl_xor_sync(0xffffffffu, p1[mt], 2);
    }
    if (tig == 0) {
#pragma unroll
        for (int mt = 0; mt < 2; mt++) {
            s_part[mt * 16 + gid][wid]     = p0[mt];
            s_part[mt * 16 + gid + 8][wid] = p1[mt];
        }
    }
    __syncthreads();

    if (t < 32) {
        float a = 0.f;
#pragma unroll
        for (int h = 0; h < N_HEADS; h++) {
            float logit = s_part[t][2 * h] + s_part[t][2 * h + 1] + __ldg(bh2 + h);
            a += __ldg(Wfuse + h) / (1.f + expf(-logit));
        }
        s_attn[t] = a;
    }
    __syncthreads();

    for (int i = t; i < 32 * 32; i += 256) {
        int r = i >> 5, c4 = i & 31;
        int gr = row0 + r;
        if (gr < N_HE) {
            float4 v = ((const float4*)g_he_feat)[(size_t)gr * 32 + c4];
            float a = s_attn[r];
            v.x *= a; v.y *= a; v.z *= a; v.w *= a;
            ((float4*)g_he_w)[(size_t)gr * 32 + c4] = v;
        }
    }
}

// ---------------------------------------------------------------------------
__global__ void ovf_kernel() {
    int novf = g_novf;
    if (novf > OVF_CAP) novf = OVF_CAP;
    int widg = (blockIdx.x * blockDim.x + threadIdx.x) >> 5;
    int lane = threadIdx.x & 31;
    int nw = (gridDim.x * blockDim.x) >> 5;
    for (int e = widg; e < novf; e += nw) {
        float4 o = g_ovf[e];
        int p = __float_as_int(o.x);
        int h = __float_as_int(o.y);
        float w = o.z;
        float4 v = ((const float4*)(g_he_w + (size_t)h * D_IN))[lane];
        red_add_v4(g_cluster + (size_t)p * D_IN + lane * 4,
                   v.x * w, v.y * w, v.z * w, v.w * w);
    }
}

// ---------------------------------------------------------------------------
__global__ __launch_bounds__(256) void p_acc_kernel(int nP) {
    __shared__ float2 s_list[8][P_CAP];
    int wid = threadIdx.x >> 5, lane = threadIdx.x & 31;
    int p = blockIdx.x * 8 + wid;
    if (p >= nP) return;
    int n = g_cnt_p[p];
    if (n > P_CAP) n = P_CAP;
    for (int i = lane; i < n; i += 32) s_list[wid][i] = g_list_p[(size_t)p * P_CAP + i];
    __syncwarp();

    float4 acc = make_float4(0.f, 0.f, 0.f, 0.f);
    if (g_novf > 0)
        acc = ((const float4*)(g_cluster + (size_t)p * D_IN))[lane];

    const float4* hw4 = (const float4*)g_he_w;
    int i = 0;
    for (; i + 4 <= n; i += 4) {
        float2 e0 = s_list[wid][i],     e1 = s_list[wid][i + 1];
        float2 e2 = s_list[wid][i + 2], e3 = s_list[wid][i + 3];
        float4 v0 = hw4[(size_t)__float_as_int(e0.x) * 32 + lane];
        float4 v1 = hw4[(size_t)__float_as_int(e1.x) * 32 + lane];
        float4 v2 = hw4[(size_t)__float_as_int(e2.x) * 32 + lane];
        float4 v3 = hw4[(size_t)__float_as_int(e3.x) * 32 + lane];
        acc.x += e0.y * v0.x; acc.y += e0.y * v0.y; acc.z += e0.y * v0.z; acc.w += e0.y * v0.w;
        acc.x += e1.y * v1.x; acc.y += e1.y * v1.y; acc.z += e1.y * v1.z; acc.w += e1.y * v1.w;
        acc.x += e2.y * v2.x; acc.y += e2.y * v2.y; acc.z += e2.y * v2.z; acc.w += e2.y * v2.w;
        acc.x += e3.y * v3.x; acc.y += e3.y * v3.y; acc.z += e3.y * v3.z; acc.w += e3.y * v3.w;
    }
    for (; i < n; i++) {
        float2 e0 = s_list[wid][i];
        float4 v0 = hw4[(size_t)__float_as_int(e0.x) * 32 + lane];
        acc.x += e0.y * v0.x; acc.y += e0.y * v0.y; acc.z += e0.y * v0.z; acc.w += e0.y * v0.w;
    }
    ((float4*)(g_cluster + (size_t)p * D_IN))[lane] = acc;
}

// ---------------------------------------------------------------------------
// fused MLP, bf16-split, 32 rows/block, fragment-packed B operands
// ---------------------------------------------------------------------------
#define R1OFF 0
#define R2OFF 8704
#define R3OFF 25600
#define GATEOFF 42496
#define LO128 (32 * PB128)
#define LO256 (32 * PB256)

__global__ __launch_bounds__(256, 2) void mlp2_kernel(
    const float* __restrict__ feat,
    const float* __restrict__ bself, const float* __restrict__ bclu,
    const float* __restrict__ bf1,   const float* __restrict__ bf2,
    const float* __restrict__ Wf3,   const float* __restrict__ bf3,
    float* __restrict__ out, int nP) {
    extern __shared__ unsigned short s16[];
    unsigned short* r1 = s16 + R1OFF;
    unsigned short* r2 = s16 + R2OFF;
    unsigned short* r3 = s16 + R3OFF;
    float (*s_gate)[2] = (float (*)[2])(s16 + GATEOFF);
    float* s_x2 = (float*)r2;

    int row0 = blockIdx.x * 32;
    int t = threadIdx.x;
    int wid = t >> 5, lane = t & 31;

    load_tile_planes(r1, PB128, LO128, (const float4*)feat, row0, nP, t);
    load_tile_planes(r2, PB256, LO256, (const float4*)g_cluster, row0, nP, t);
    __syncthreads();

    int m8 = lane >> 3, rIn = lane & 7;
    int rowoff = (m8 & 1) * 8 + rIn;
    int colByte = (m8 >> 1) * 16;
    int gid = lane >> 2, tig = lane & 3;

    // stage A: self_f | clu_f
    {
        float acc[2][4][4];
#pragma unroll
        for (int a = 0; a < 2; a++)
#pragma unroll
            for (int b = 0; b < 4; b++)
#pragma unroll
                for (int c = 0; c < 4; c++) acc[a][b][c] = 0.f;

        unsigned short* aBuf = (wid < 4) ? r1 : r2;
        int aStr             = (wid < 4) ? PB128 : PB256;
        unsigned loOff       = (wid < 4) ? (LO128 * 2) : (LO256 * 2);
        int wOff             = (wid < 4) ? OFF_WSELF : OFF_WCLU;
        const float* bias    = (wid < 4) ? bself : bclu;
        int ncol0            = (wid & 3) * 32;
        int outcol0          = (wid < 4) ? ncol0 : (128 + ncol0);

        unsigned aAddr[2];
#pragma unroll
        for (int mt = 0; mt < 2; mt++)
            aAddr[mt] = smem_u32(aBuf + (mt * 16 + rowoff) * aStr) + colByte;

        size_t fidx = ((size_t)((wid & 3) * 8) * 32 + lane) * 2;
        const uint4* Bhi = (const uint4*)(g_Whi + wOff) + fidx;
        const uint4* Blo = (const uint4*)(g_Wlo + wOff) + fidx;
        gemm_bf16<8, 4, 2>(aAddr, loOff, Bhi, Blo, acc);
        __syncthreads();
        epilogue_bf16<4, 2, false>(r3, PB256, LO256, outcol0, bias + ncol0, acc, lane);
    }
    __syncthreads();

    // stage B: x1 = relu(cat @ Wf1 + bf1)
    {
        float acc[2][4][4];
#pragma unroll
        for (int a = 0; a < 2; a++)
#pragma unroll
            for (int b = 0; b < 4; b++)
#pragma unroll
                for (int c = 0; c < 4; c++) acc[a][b][c] = 0.f;

        int ncol0 = wid * 32;
        unsigned aAddr[2];
#pragma unroll
        for (int mt = 0; mt < 2; mt++)
            aAddr[mt] = smem_u32(r3 + (mt * 16 + rowoff) * PB256) + colByte;
        size_t fidx = ((size_t)(wid * 16) * 32 + lane) * 2;
        const uint4* Bhi = (const uint4*)(g_Whi + OFF_WF1) + fidx;
        const uint4* Blo = (const uint4*)(g_Wlo + OFF_WF1) + fidx;
        gemm_bf16<16, 4, 2>(aAddr, LO256 * 2, Bhi, Blo, acc);
        __syncthreads();
        epilogue_bf16<4, 2, true>(r2, PB256, LO256, ncol0, bf1 + ncol0, acc, lane);
    }
    __syncthreads();

    // stage C: x2 = relu(x1 @ Wf2 + bf2)
    {
        float acc[2][2][4];
#pragma unroll
        for (int a = 0; a < 2; a++)
#pragma unroll
            for (int b = 0; b < 2; b++)
#pragma unroll
                for (int c = 0; c < 4; c++) acc[a][b][c] = 0.f;

        int ncol0 = wid * 16;
        unsigned aAddr[2];
#pragma unroll
        for (int mt = 0; mt < 2; mt++)
            aAddr[mt] = smem_u32(r2 + (mt * 16 + rowoff) * PB256) + colByte;
        size_t fidx = ((size_t)(wid * 16) * 32 + lane) * 1;
        const uint4* Bhi = (const uint4*)(g_Whi + OFF_WF2) + fidx;
        const uint4* Blo = (const uint4*)(g_Wlo + OFF_WF2) + fidx;
        gemm_bf16<16, 2, 2>(aAddr, LO256 * 2, Bhi, Blo, acc);
        __syncthreads();
        epilogue_f32<2, 2, true>(s_x2, 132, ncol0, bf2 + ncol0, acc, lane);
    }
    __syncthreads();

    // stage D: logits + softmax gates
    if (t < 64) {
        int r = t >> 1, l = t & 1;
        float a = __ldg(bf3 + l);
        const float* x = s_x2 + (size_t)r * 132;
#pragma unroll 4
        for (int k = 0; k < 128; k++)
            a += x[k] * __ldg(Wf3 + 2 * k + l);
        s_gate[r][l] = a;
    }
    __syncthreads();
    if (t < 32) {
        float a = s_gate[t][0], b = s_gate[t][1];
        float m = fmaxf(a, b);
        float e0 = expf(a - m), e1 = expf(b - m);
        float inv = 1.f / (e0 + e1);
        s_gate[t][0] = e0 * inv;
        s_gate[t][1] = e1 * inv;
    }
    __syncthreads();

    // stage E
    const float4* feat4 = (const float4*)feat;
    for (int i = t; i < 32 * 32; i += 256) {
        int r = i >> 5, c4 = i & 31;
        int gr = row0 + r;
        if (gr < nP) {
            float4 f = feat4[(size_t)gr * 32 + c4];
            float g0 = s_gate[r][0], g1 = s_gate[r][1];
            int c0 = c4 * 4;
            ushort4 hs = *(const ushort4*)&r3[r * PB256 + c0];
            ushort4 ls = *(const ushort4*)&r3[LO256 + r * PB256 + c0];
            ushort4 hc = *(const ushort4*)&r3[r * PB256 + c0 + 128];
            ushort4 lc = *(const ushort4*)&r3[LO256 + r * PB256 + c0 + 128];
            float4 o;
            o.x = fmaxf((bfu(hs.x) + bfu(ls.x)) * g0 + (bfu(hc.x) + bfu(lc.x)) * g1 + f.x, 0.f);
            o.y = fmaxf((bfu(hs.y) + bfu(ls.y)) * g0 + (bfu(hc.y) + bfu(lc.y)) * g1 + f.y, 0.f);
            o.z = fmaxf((bfu(hs.z) + bfu(ls.z)) * g0 + (bfu(hc.z) + bfu(lc.z)) * g1 + f.z, 0.f);
            o.w = fmaxf((bfu(hs.w) + bfu(ls.w)) * g0 + (bfu(hc.w) + bfu(lc.w)) * g1 + f.w, 0.f);
            ((float4*)out)[(size_t)gr * 32 + c4] = o;
        }
    }
}

// ---------------------------------------------------------------------------
extern "C" void kernel_launch(void* const* d_in, const int* in_sizes, int n_in,
                              void* d_out, int out_size) {
    const float* feat   = (const float*)d_in[0];
    const float* edge_w = (const float*)d_in[1];
    const float* Wself  = (const float*)d_in[2];
    const float* bself  = (const float*)d_in[3];
    const float* Wclu   = (const float*)d_in[4];
    const float* bclu   = (const float*)d_in[5];
    const float* Wh1    = (const float*)d_in[6];
    const float* bh1    = (const float*)d_in[7];
    const float* Wh2    = (const float*)d_in[8];
    const float* bh2    = (const float*)d_in[9];
    const float* Wfuse  = (const float*)d_in[10];
    const float* Wf1    = (const float*)d_in[11];
    const float* bf1    = (const float*)d_in[12];
    const float* Wf2    = (const float*)d_in[13];
    const float* bf2    = (const float*)d_in[14];
    const float* Wf3    = (const float*)d_in[15];
    const float* bf3    = (const float*)d_in[16];
    const int*   e_pid  = (const int*)d_in[17];
    const int*   e_hid  = (const int*)d_in[18];

    int nE = in_sizes[17];
    int nP = in_sizes[0] / D_IN;
    float* out = (float*)d_out;

    int zpN = N_HE * (D_IN / 4);
    zero_pack_kernel<<<(zpN + 255) / 256, 256>>>(Wself, Wclu, Wf1, Wf2, Wh1);

    fill_kernel<<<(nE + 255) / 256, 256>>>(edge_w, e_pid, e_hid, feat, nE);

    zero_cluster_kernel<<<592, 256>>>();

    he_acc_kernel<<<(N_HE + 7) / 8, 256>>>(feat);

    attn_gemm_kernel<<<(N_HE + 31) / 32, 256>>>(bh1, Wh2, bh2, Wfuse);

    ovf_kernel<<<32, 256>>>();

    p_acc_kernel<<<(nP + 7) / 8, 256>>>(nP);

    size_t smemBytes = (size_t)GATEOFF * 2 + 32 * 2 * sizeof(float);
    cudaFuncSetAttribute(mlp2_kernel, cudaFuncAttributeMaxDynamicSharedMemorySize,
                         (int)smemBytes);
    int nBlocks = (nP + 31) / 32;
    mlp2_kernel<<<nBlocks, 256, smemBytes>>>(feat, bself, bclu, bf1, bf2,
                                             Wf3, bf3, out, nP);
}

// round 17
// speedup vs baseline: 1.1894x; 1.1406x over previous
#include <cuda_runtime.h>
#include <cuda_bf16.h>
#include <math.h>

#define N_P   50000
#define N_HE  5000
#define D_IN  128
#define D_HID 256
#define N_HEADS 4
#define HEAD_DIM 64

#define HE_CAP 256
#define P_CAP  64
#define OVF_CAP 65536

// bf16 plane strides (in bf16 elems): row bytes odd multiple of 16
#define PB128 136
#define PB256 264

// packed-weight sections (u32), fragment-order layout (see pack kernel)
#define OFF_WSELF 0
#define OFF_WCLU  8192
#define OFF_WF1   16384
#define OFF_WF2   49152
#define OFF_WH1   65536
#define PACK_TOTAL 81920

// ---- scratch (no allocation allowed) ----
__device__ float g_he_feat[N_HE * D_IN];
__device__ float g_he_w[N_HE * D_IN];
__device__ float g_cluster[N_P * D_IN];
__device__ int   g_cnt_he[N_HE];
__device__ int   g_cnt_p[N_P];
__device__ float2 g_list_he[N_HE * HE_CAP];
__device__ float2 g_list_p[N_P * P_CAP];
__device__ float4 g_ovf[OVF_CAP];
__device__ int   g_novf;
__device__ __align__(16) unsigned g_Whi[PACK_TOTAL];
__device__ __align__(16) unsigned g_Wlo[PACK_TOTAL];

// ---------------------------------------------------------------------------
__device__ __forceinline__ void red_add_v4(float* dst, float a, float b, float c, float d) {
    asm volatile("red.global.add.v4.f32 [%0], {%1,%2,%3,%4};"
                 :: "l"(dst), "f"(a), "f"(b), "f"(c), "f"(d) : "memory");
}

__device__ __forceinline__ void split_pack(float x0, float x1, unsigned& hi, unsigned& lo) {
    __nv_bfloat16 h0 = __float2bfloat16(x0);
    __nv_bfloat16 h1 = __float2bfloat16(x1);
    __nv_bfloat16 l0 = __float2bfloat16(x0 - __bfloat162float(h0));
    __nv_bfloat16 l1 = __float2bfloat16(x1 - __bfloat162float(h1));
    hi = (unsigned)__bfloat16_as_ushort(h0) | ((unsigned)__bfloat16_as_ushort(h1) << 16);
    lo = (unsigned)__bfloat16_as_ushort(l0) | ((unsigned)__bfloat16_as_ushort(l1) << 16);
}

__device__ __forceinline__ float bfu(unsigned short u) {
    return __bfloat162float(__ushort_as_bfloat16(u));
}

// ---------------------------------------------------------------------------
// zero (he_feat + counters) fused with FRAGMENT-ORDER weight packing
// ---------------------------------------------------------------------------
__global__ void zero_pack_kernel(const float* __restrict__ Wself, const float* __restrict__ Wclu,
                                 const float* __restrict__ Wf1,   const float* __restrict__ Wf2,
                                 const float* __restrict__ Wh1) {
    int i = blockIdx.x * blockDim.x + threadIdx.x;
    if (i < N_HE * (D_IN / 4))
        ((float4*)g_he_feat)[i] = make_float4(0.f, 0.f, 0.f, 0.f);
    if (i < N_HE) g_cnt_he[i] = 0;
    if (i < N_P)  g_cnt_p[i] = 0;
    if (i == 0)   g_novf = 0;
    if (i < PACK_TOTAL) {
        const float* W;
        int N, K, NT, local;
        if (i < OFF_WCLU)      { W = Wself; N = 128; K = 128; NT = 4; local = i; }
        else if (i < OFF_WF1)  { W = Wclu;  N = 128; K = 128; NT = 4; local = i - OFF_WCLU; }
        else if (i < OFF_WF2)  { W = Wf1;   N = 256; K = 256; NT = 4; local = i - OFF_WF1; }
        else if (i < OFF_WH1)  { W = Wf2;   N = 128; K = 256; NT = 2; local = i - OFF_WF2; }
        else {
            local = i - OFF_WH1;
            int head = local / 4096; local -= head * 4096;
            W = Wh1 + (size_t)head * 128 * 64; N = 64; K = 128; NT = 4;
        }
        int KT = K / 16;
        int twoNT = 2 * NT;
        int j = local % twoNT;  int r = local / twoNT;
        int lane = r % 32;      r /= 32;
        int kt = r % KT;        int wb = r / KT;
        int tig = lane & 3, gid = lane >> 2;
        int nt = (j < NT) ? j : j - NT;
        int k2 = kt * 8 + ((j < NT) ? 0 : 4) + tig;
        int n  = wb * NT * 8 + nt * 8 + gid;
        unsigned hi, lo;
        split_pack(W[(size_t)(2 * k2) * N + n], W[(size_t)(2 * k2 + 1) * N + n], hi, lo);
        g_Whi[i] = hi;
        g_Wlo[i] = lo;
    }
}

// ---------------------------------------------------------------------------
__global__ void fill_kernel(const float* __restrict__ ew,
                            const int* __restrict__ pid,
                            const int* __restrict__ hid,
                            const float* __restrict__ feat, int nE) {
    int e = blockIdx.x * blockDim.x + threadIdx.x;
    if (e >= nE) return;
    int p = pid[e];
    int h = hid[e];
    float w = ew[e];

    int pos = atomicAdd(&g_cnt_he[h], 1);
    if (pos < HE_CAP) {
        g_list_he[(size_t)h * HE_CAP + pos] = make_float2(__int_as_float(p), w);
    } else {
        const float4* fr = (const float4*)(feat + (size_t)p * D_IN);
        for (int i = 0; i < D_IN / 4; i++) {
            float4 v = fr[i];
            red_add_v4(g_he_feat + (size_t)h * D_IN + i * 4,
                       v.x * w, v.y * w, v.z * w, v.w * w);
        }
    }

    int pos2 = atomicAdd(&g_cnt_p[p], 1);
    if (pos2 < P_CAP) {
        g_list_p[(size_t)p * P_CAP + pos2] = make_float2(__int_as_float(h), w);
    } else {
        int o = atomicAdd(&g_novf, 1);
        if (o < OVF_CAP)
            g_ovf[o] = make_float4(__int_as_float(p), __int_as_float(h), w, 0.f);
    }
}

// ---------------------------------------------------------------------------
// conditional cluster zero (grid-stride; early-exits when no overflow)
// ---------------------------------------------------------------------------
__global__ void zero_cluster_kernel() {
    if (g_novf == 0) return;
    int stride = gridDim.x * blockDim.x;
    for (int i = blockIdx.x * blockDim.x + threadIdx.x;
         i < N_P * (D_IN / 4); i += stride)
        ((float4*)g_cluster)[i] = make_float4(0.f, 0.f, 0.f, 0.f);
}

// ---------------------------------------------------------------------------
// he_acc: warp per hyperedge, unroll 4 (measured-best form, 29.4us)
// ---------------------------------------------------------------------------
__global__ __launch_bounds__(256) void he_acc_kernel(const float* __restrict__ feat) {
    __shared__ float2 s_list[8][HE_CAP];
    int wid = threadIdx.x >> 5, lane = threadIdx.x & 31;
    int he = blockIdx.x * 8 + wid;
    if (he >= N_HE) return;
    int n_raw = g_cnt_he[he];
    int n = n_raw < HE_CAP ? n_raw : HE_CAP;
    for (int i = lane; i < n; i += 32) s_list[wid][i] = g_list_he[(size_t)he * HE_CAP + i];
    __syncwarp();

    float4 acc = make_float4(0.f, 0.f, 0.f, 0.f);
    if (n_raw > HE_CAP)
        acc = ((const float4*)(g_he_feat + (size_t)he * D_IN))[lane];

    const float4* feat4 = (const float4*)feat;
    int i = 0;
    for (; i + 4 <= n; i += 4) {
        float2 e0 = s_list[wid][i],     e1 = s_list[wid][i + 1];
        float2 e2 = s_list[wid][i + 2], e3 = s_list[wid][i + 3];
        float4 v0 = feat4[(size_t)__float_as_int(e0.x) * 32 + lane];
        float4 v1 = feat4[(size_t)__float_as_int(e1.x) * 32 + lane];
        float4 v2 = feat4[(size_t)__float_as_int(e2.x) * 32 + lane];
        float4 v3 = feat4[(size_t)__float_as_int(e3.x) * 32 + lane];
        acc.x += e0.y * v0.x; acc.y += e0.y * v0.y; acc.z += e0.y * v0.z; acc.w += e0.y * v0.w;
        acc.x += e1.y * v1.x; acc.y += e1.y * v1.y; acc.z += e1.y * v1.z; acc.w += e1.y * v1.w;
        acc.x += e2.y * v2.x; acc.y += e2.y * v2.y; acc.z += e2.y * v2.z; acc.w += e2.y * v2.w;
        acc.x += e3.y * v3.x; acc.y += e3.y * v3.y; acc.z += e3.y * v3.z; acc.w += e3.y * v3.w;
    }
    for (; i < n; i++) {
        float2 e0 = s_list[wid][i];
        float4 v0 = feat4[(size_t)__float_as_int(e0.x) * 32 + lane];
        acc.x += e0.y * v0.x; acc.y += e0.y * v0.y; acc.z += e0.y * v0.z; acc.w += e0.y * v0.w;
    }
    ((float4*)(g_he_feat + (size_t)he * D_IN))[lane] = acc;
}

// ---------------------------------------------------------------------------
// bf16 MMA machinery; B fragment-packed (LDG.128), A double-buffered LDSM
// ---------------------------------------------------------------------------
__device__ __forceinline__ void mma_bf16(float (&c)[4], const unsigned (&a)[4],
                                         unsigned b0, unsigned b1) {
    asm volatile(
        "mma.sync.aligned.m16n8k16.row.col.f32.bf16.bf16.f32 "
        "{%0,%1,%2,%3},{%4,%5,%6,%7},{%8,%9},{%0,%1,%2,%3};\n"
        : "+f"(c[0]), "+f"(c[1]), "+f"(c[2]), "+f"(c[3])
        : "r"(a[0]), "r"(a[1]), "r"(a[2]), "r"(a[3]), "r"(b0), "r"(b1));
}

#define LDSM4(R, ADDR) \
    asm volatile("ldmatrix.sync.aligned.m8n8.x4.shared.b16 {%0,%1,%2,%3},[%4];" \
                 : "=r"((R)[0]), "=r"((R)[1]), "=r"((R)[2]), "=r"((R)[3]) : "r"(ADDR))

__device__ __forceinline__ unsigned smem_u32(const void* p) {
    return (unsigned)__cvta_generic_to_shared(p);
}

template <int KT, int NT, int MT>
__device__ __forceinline__ void gemm_bf16(const unsigned (&aAddr)[MT], unsigned loOffBytes,
                                          const uint4* __restrict__ Bhi,
                                          const uint4* __restrict__ Blo,
                                          float (&acc)[MT][NT][4]) {
    constexpr int NB4 = NT / 2;
    unsigned ah0[MT][4], al0[MT][4];
    unsigned bh0[2 * NT], bl0[2 * NT];
#pragma unroll
    for (int mt = 0; mt < MT; mt++) {
        LDSM4(ah0[mt], aAddr[mt]);
        LDSM4(al0[mt], aAddr[mt] + loOffBytes);
    }
#pragma unroll
    for (int q = 0; q < NB4; q++) {
        uint4 vh = __ldg(Bhi + q), vl = __ldg(Blo + q);
        bh0[4 * q + 0] = vh.x; bh0[4 * q + 1] = vh.y; bh0[4 * q + 2] = vh.z; bh0[4 * q + 3] = vh.w;
        bl0[4 * q + 0] = vl.x; bl0[4 * q + 1] = vl.y; bl0[4 * q + 2] = vl.z; bl0[4 * q + 3] = vl.w;
    }
#pragma unroll
    for (int kt = 0; kt < KT; kt++) {
        unsigned ah1[MT][4], al1[MT][4];
        unsigned bh1[2 * NT], bl1[2 * NT];
        if (kt + 1 < KT) {
#pragma unroll
            for (int mt = 0; mt < MT; mt++) {
                LDSM4(ah1[mt], aAddr[mt] + (kt + 1) * 32u);
                LDSM4(al1[mt], aAddr[mt] + loOffBytes + (kt + 1) * 32u);
            }
#pragma unroll
            for (int q = 0; q < NB4; q++) {
                uint4 vh = __ldg(Bhi + (size_t)(kt + 1) * 32 * NB4 + q);
                uint4 vl = __ldg(Blo + (size_t)(kt + 1) * 32 * NB4 + q);
                bh1[4 * q + 0] = vh.x; bh1[4 * q + 1] = vh.y; bh1[4 * q + 2] = vh.z; bh1[4 * q + 3] = vh.w;
                bl1[4 * q + 0] = vl.x; bl1[4 * q + 1] = vl.y; bl1[4 * q + 2] = vl.z; bl1[4 * q + 3] = vl.w;
            }
        }
#pragma unroll
        for (int nt = 0; nt < NT; nt++)
#pragma unroll
            for (int mt = 0; mt < MT; mt++) {
                mma_bf16(acc[mt][nt], al0[mt], bh0[nt], bh0[NT + nt]);
                mma_bf16(acc[mt][nt], ah0[mt], bl0[nt], bl0[NT + nt]);
                mma_bf16(acc[mt][nt], ah0[mt], bh0[nt], bh0[NT + nt]);
            }
#pragma unroll
        for (int mt = 0; mt < MT; mt++)
#pragma unroll
            for (int i = 0; i < 4; i++) { ah0[mt][i] = ah1[mt][i]; al0[mt][i] = al1[mt][i]; }
#pragma unroll
        for (int j = 0; j < 2 * NT; j++) { bh0[j] = bh1[j]; bl0[j] = bl1[j]; }
    }
}

template <int NT, int MT, bool RELU>
__device__ __forceinline__ void epilogue_bf16(unsigned short* hiBase, int strideElems,
                                              int loOffElems, int col0,
                                              const float* __restrict__ bias,
                                              float (&acc)[MT][NT][4], int lane) {
    int gid = lane >> 2, tig = lane & 3;
#pragma unroll
    for (int nt = 0; nt < NT; nt++) {
        int c = nt * 8 + tig * 2;
        float bA = __ldg(bias + c), bB = __ldg(bias + c + 1);
#pragma unroll
        for (int mt = 0; mt < MT; mt++) {
            int r = mt * 16 + gid;
            float v0 = acc[mt][nt][0] + bA, v1 = acc[mt][nt][1] + bB;
            float v2 = acc[mt][nt][2] + bA, v3 = acc[mt][nt][3] + bB;
            if (RELU) {
                v0 = fmaxf(v0, 0.f); v1 = fmaxf(v1, 0.f);
                v2 = fmaxf(v2, 0.f); v3 = fmaxf(v3, 0.f);
            }
            unsigned h01, l01, h23, l23;
            split_pack(v0, v1, h01, l01);
            split_pack(v2, v3, h23, l23);
            int i0 = r * strideElems + col0 + c;
            int i1 = (r + 8) * strideElems + col0 + c;
            *(unsigned*)&hiBase[i0]               = h01;
            *(unsigned*)&hiBase[loOffElems + i0]  = l01;
            *(unsigned*)&hiBase[i1]               = h23;
            *(unsigned*)&hiBase[loOffElems + i1]  = l23;
        }
    }
}

__device__ __forceinline__ void load_tile_planes(unsigned short* plane, int strideElems,
                                                 int loOffElems, const float4* src,
                                                 int row0, int rowMax, int t) {
    for (int i = t; i < 32 * 32; i += 256) {
        int r = i >> 5, c4 = i & 31;
        int gr = row0 + r;
        float4 v = make_float4(0.f, 0.f, 0.f, 0.f);
        if (gr < rowMax) v = src[(size_t)gr * 32 + c4];
        unsigned h01, l01, h23, l23;
        split_pack(v.x, v.y, h01, l01);
        split_pack(v.z, v.w, h23, l23);
        int base = r * strideElems + c4 * 4;
        *(unsigned*)&plane[base]                   = h01;
        *(unsigned*)&plane[base + 2]               = h23;
        *(unsigned*)&plane[loOffElems + base]      = l01;
        *(unsigned*)&plane[loOffElems + base + 2]  = l23;
    }
}

// ---------------------------------------------------------------------------
// attention: 32-row tiles, bf16-split GEMM vs fragment-packed Wh1
// ---------------------------------------------------------------------------
__global__ __launch_bounds__(256) void attn_gemm_kernel(
    const float* __restrict__ bh1, const float* __restrict__ Wh2,
    const float* __restrict__ bh2, const float* __restrict__ Wfuse) {
    __shared__ unsigned short s_he[2 * 32 * PB128];
    __shared__ float s_part[32][8];
    __shared__ float s_attn[32];

    int row0 = blockIdx.x * 32;
    int t = threadIdx.x, wid = t >> 5, lane = t & 31;

    load_tile_planes(s_he, PB128, 32 * PB128, (const float4*)g_he_feat, row0, N_HE, t);
    __syncthreads();

    int m8 = lane >> 3, rIn = lane & 7;
    int rowoff = (m8 & 1) * 8 + rIn;
    int colByte = (m8 >> 1) * 16;
    int gid = lane >> 2, tig = lane & 3;

    int head = wid >> 1;
    int colHalf = (wid & 1) * 32;

    float acc[2][4][4];
#pragma unroll
    for (int a = 0; a < 2; a++)
#pragma unroll
        for (int b = 0; b < 4; b++)
#pragma unroll
            for (int c = 0; c < 4; c++) acc[a][b][c] = 0.f;

    unsigned aAddr[2];
#pragma unroll
    for (int mt = 0; mt < 2; mt++)
        aAddr[mt] = smem_u32(s_he + (mt * 16 + rowoff) * PB128) + colByte;

    size_t fidx = ((size_t)((wid & 1) * 8) * 32 + lane) * 2;
    const uint4* Bhi = (const uint4*)(g_Whi + OFF_WH1 + head * 4096) + fidx;
    const uint4* Blo = (const uint4*)(g_Wlo + OFF_WH1 + head * 4096) + fidx;
    gemm_bf16<8, 4, 2>(aAddr, 32 * PB128 * 2, Bhi, Blo, acc);

    float p0[2] = {0.f, 0.f};
    float p1[2] = {0.f, 0.f};
#pragma unroll
    for (int nt = 0; nt < 4; nt++) {
        int c = head * HEAD_DIM + colHalf + nt * 8 + tig * 2;
        float bA = __ldg(bh1 + c),  bB = __ldg(bh1 + c + 1);
        float wA = __ldg(Wh2 + c),  wB = __ldg(Wh2 + c + 1);
#pragma unroll
        for (int mt = 0; mt < 2; mt++) {
            p0[mt] += fmaxf(acc[mt][nt][0] + bA, 0.f) * wA
                    + fmaxf(acc[mt][nt][1] + bB, 0.f) * wB;
            p1[mt] += fmaxf(acc[mt][nt][2] + bA, 0.f) * wA
                    + fmaxf(acc[mt][nt][3] + bB, 0.f) * wB;
        }
    }
#pragma unroll
    for (int mt = 0; mt < 2; mt++) {
        p0[mt] += __shfl_xor_sync(0xffffffffu, p0[mt], 1);
        p0[mt] += __shfl_xor_sync(0xffffffffu, p0[mt], 2);
        p1[mt] += __shfl_xor_sync(0xffffffffu, p1[mt], 1);
        p1[mt] += __shfl_xor_sync(0xffffffffu, p1[mt], 2);
    }
    if (tig == 0) {
#pragma unroll
        for (int mt = 0; mt < 2; mt++) {
            s_part[mt * 16 + gid][wid]     = p0[mt];
            s_part[mt * 16 + gid + 8][wid] = p1[mt];
        }
    }
    __syncthreads();

    if (t < 32) {
        float a = 0.f;
#pragma unroll
        for (int h = 0; h < N_HEADS; h++) {
            float logit = s_part[t][2 * h] + s_part[t][2 * h + 1] + __ldg(bh2 + h);
            a += __ldg(Wfuse + h) / (1.f + expf(-logit));
        }
        s_attn[t] = a;
    }
    __syncthreads();

    for (int i = t; i < 32 * 32; i += 256) {
        int r = i >> 5, c4 = i & 31;
        int gr = row0 + r;
        if (gr < N_HE) {
            float4 v = ((const float4*)g_he_feat)[(size_t)gr * 32 + c4];
            float a = s_attn[r];
            v.x *= a; v.y *= a; v.z *= a; v.w *= a;
            ((float4*)g_he_w)[(size_t)gr * 32 + c4] = v;
        }
    }
}

// ---------------------------------------------------------------------------
__global__ void ovf_kernel() {
    int novf = g_novf;
    if (novf > OVF_CAP) novf = OVF_CAP;
    int widg = (blockIdx.x * blockDim.x + threadIdx.x) >> 5;
    int lane = threadIdx.x & 31;
    int nw = (gridDim.x * blockDim.x) >> 5;
    for (int e = widg; e < novf; e += nw) {
        float4 o = g_ovf[e];
        int p = __float_as_int(o.x);
        int h = __float_as_int(o.y);
        float w = o.z;
        float4 v = ((const float4*)(g_he_w + (size_t)h * D_IN))[lane];
        red_add_v4(g_cluster + (size_t)p * D_IN + lane * 4,
                   v.x * w, v.y * w, v.z * w, v.w * w);
    }
}

// ---------------------------------------------------------------------------
__global__ __launch_bounds__(256) void p_acc_kernel(int nP) {
    __shared__ float2 s_list[8][P_CAP];
    int wid = threadIdx.x >> 5, lane = threadIdx.x & 31;
    int p = blockIdx.x * 8 + wid;
    if (p >= nP) return;
    int n = g_cnt_p[p];
    if (n > P_CAP) n = P_CAP;
    for (int i = lane; i < n; i += 32) s_list[wid][i] = g_list_p[(size_t)p * P_CAP + i];
    __syncwarp();

    float4 acc = make_float4(0.f, 0.f, 0.f, 0.f);
    if (g_novf > 0)
        acc = ((const float4*)(g_cluster + (size_t)p * D_IN))[lane];

    const float4* hw4 = (const float4*)g_he_w;
    int i = 0;
    for (; i + 4 <= n; i += 4) {
        float2 e0 = s_list[wid][i],     e1 = s_list[wid][i + 1];
        float2 e2 = s_list[wid][i + 2], e3 = s_list[wid][i + 3];
        float4 v0 = hw4[(size_t)__float_as_int(e0.x) * 32 + lane];
        float4 v1 = hw4[(size_t)__float_as_int(e1.x) * 32 + lane];
        float4 v2 = hw4[(size_t)__float_as_int(e2.x) * 32 + lane];
        float4 v3 = hw4[(size_t)__float_as_int(e3.x) * 32 + lane];
        acc.x += e0.y * v0.x; acc.y += e0.y * v0.y; acc.z += e0.y * v0.z; acc.w += e0.y * v0.w;
        acc.x += e1.y * v1.x; acc.y += e1.y * v1.y; acc.z += e1.y * v1.z; acc.w += e1.y * v1.w;
        acc.x += e2.y * v2.x; acc.y += e2.y * v2.y; acc.z += e2.y * v2.z; acc.w += e2.y * v2.w;
        acc.x += e3.y * v3.x; acc.y += e3.y * v3.y; acc.z += e3.y * v3.z; acc.w += e3.y * v3.w;
    }
    for (; i < n; i++) {
        float2 e0 = s_list[wid][i];
        float4 v0 = hw4[(size_t)__float_as_int(e0.x) * 32 + lane];
        acc.x += e0.y * v0.x; acc.y += e0.y * v0.y; acc.z += e0.y * v0.z; acc.w += e0.y * v0.w;
    }
    ((float4*)(g_cluster + (size_t)p * D_IN))[lane] = acc;
}

// ---------------------------------------------------------------------------
// fused MLP, bf16-split, 32 rows/block, fragment-packed B operands.
// Stage D (x2 @ Wf3) fused into stage C's register epilogue: no x2 smem,
// 2 fewer barriers.
// ---------------------------------------------------------------------------
#define R1OFF 0
#define R2OFF 8704
#define R3OFF 25600
#define GATEOFF 42496            // float[32][2] gates = 128 u16
#define DPARTOFF (GATEOFF + 128) // float[32][8][2] partials = 1024 u16
#define SMEM_U16 (DPARTOFF + 1024)
#define LO128 (32 * PB128)
#define LO256 (32 * PB256)

__global__ __launch_bounds__(256, 2) void mlp2_kernel(
    const float* __restrict__ feat,
    const float* __restrict__ bself, const float* __restrict__ bclu,
    const float* __restrict__ bf1,   const float* __restrict__ bf2,
    const float* __restrict__ Wf3,   const float* __restrict__ bf3,
    float* __restrict__ out, int nP) {
    extern __shared__ unsigned short s16[];
    unsigned short* r1 = s16 + R1OFF;
    unsigned short* r2 = s16 + R2OFF;
    unsigned short* r3 = s16 + R3OFF;
    float (*s_gate)[2]     = (float (*)[2])(s16 + GATEOFF);
    float (*s_dpart)[8][2] = (float (*)[8][2])(s16 + DPARTOFF);

    int row0 = blockIdx.x * 32;
    int t = threadIdx.x;
    int wid = t >> 5, lane = t & 31;

    load_tile_planes(r1, PB128, LO128, (const float4*)feat, row0, nP, t);
    load_tile_planes(r2, PB256, LO256, (const float4*)g_cluster, row0, nP, t);
    __syncthreads();

    int m8 = lane >> 3, rIn = lane & 7;
    int rowoff = (m8 & 1) * 8 + rIn;
    int colByte = (m8 >> 1) * 16;
    int gid = lane >> 2, tig = lane & 3;

    // stage A: self_f | clu_f
    {
        float acc[2][4][4];
#pragma unroll
        for (int a = 0; a < 2; a++)
#pragma unroll
            for (int b = 0; b < 4; b++)
#pragma unroll
                for (int c = 0; c < 4; c++) acc[a][b][c] = 0.f;

        unsigned short* aBuf = (wid < 4) ? r1 : r2;
        int aStr             = (wid < 4) ? PB128 : PB256;
        unsigned loOff       = (wid < 4) ? (LO128 * 2) : (LO256 * 2);
        int wOff             = (wid < 4) ? OFF_WSELF : OFF_WCLU;
        const float* bias    = (wid < 4) ? bself : bclu;
        int ncol0            = (wid & 3) * 32;
        int outcol0          = (wid < 4) ? ncol0 : (128 + ncol0);

        unsigned aAddr[2];
#pragma unroll
        for (int mt = 0; mt < 2; mt++)
            aAddr[mt] = smem_u32(aBuf + (mt * 16 + rowoff) * aStr) + colByte;

        size_t fidx = ((size_t)((wid & 3) * 8) * 32 + lane) * 2;
        const uint4* Bhi = (const uint4*)(g_Whi + wOff) + fidx;
        const uint4* Blo = (const uint4*)(g_Wlo + wOff) + fidx;
        gemm_bf16<8, 4, 2>(aAddr, loOff, Bhi, Blo, acc);
        __syncthreads();
        epilogue_bf16<4, 2, false>(r3, PB256, LO256, outcol0, bias + ncol0, acc, lane);
    }
    __syncthreads();

    // stage B: x1 = relu(cat @ Wf1 + bf1)
    {
        float acc[2][4][4];
#pragma unroll
        for (int a = 0; a < 2; a++)
#pragma unroll
            for (int b = 0; b < 4; b++)
#pragma unroll
                for (int c = 0; c < 4; c++) acc[a][b][c] = 0.f;

        int ncol0 = wid * 32;
        unsigned aAddr[2];
#pragma unroll
        for (int mt = 0; mt < 2; mt++)
            aAddr[mt] = smem_u32(r3 + (mt * 16 + rowoff) * PB256) + colByte;
        size_t fidx = ((size_t)(wid * 16) * 32 + lane) * 2;
        const uint4* Bhi = (const uint4*)(g_Whi + OFF_WF1) + fidx;
        const uint4* Blo = (const uint4*)(g_Wlo + OFF_WF1) + fidx;
        gemm_bf16<16, 4, 2>(aAddr, LO256 * 2, Bhi, Blo, acc);
        __syncthreads();
        epilogue_bf16<4, 2, true>(r2, PB256, LO256, ncol0, bf1 + ncol0, acc, lane);
    }
    __syncthreads();

    // stage C+D fused: x2 = relu(x1 @ Wf2 + bf2); logits = x2 @ Wf3 in regs
    {
        float acc[2][2][4];
#pragma unroll
        for (int a = 0; a < 2; a++)
#pragma unroll
            for (int b = 0; b < 2; b++)
#pragma unroll
                for (int c = 0; c < 4; c++) acc[a][b][c] = 0.f;

        int ncol0 = wid * 16;
        unsigned aAddr[2];
#pragma unroll
        for (int mt = 0; mt < 2; mt++)
            aAddr[mt] = smem_u32(r2 + (mt * 16 + rowoff) * PB256) + colByte;
        size_t fidx = ((size_t)(wid * 16) * 32 + lane) * 1;
        const uint4* Bhi = (const uint4*)(g_Whi + OFF_WF2) + fidx;
        const uint4* Blo = (const uint4*)(g_Wlo + OFF_WF2) + fidx;
        gemm_bf16<16, 2, 2>(aAddr, LO256 * 2, Bhi, Blo, acc);

        // per-thread Wf3 dot on relu'd accumulators (no x2 smem at all)
        float pd[2][2][2];   // [mt][row-half][logit]
#pragma unroll
        for (int a = 0; a < 2; a++)
#pragma unroll
            for (int b = 0; b < 2; b++) { pd[a][b][0] = 0.f; pd[a][b][1] = 0.f; }
#pragma unroll
        for (int nt = 0; nt < 2; nt++) {
            int c = ncol0 + nt * 8 + tig * 2;
            float bA  = __ldg(bf2 + c),      bB  = __ldg(bf2 + c + 1);
            float w0a = __ldg(Wf3 + 2 * c),     w0b = __ldg(Wf3 + 2 * c + 1);
            float w1a = __ldg(Wf3 + 2 * c + 2), w1b = __ldg(Wf3 + 2 * c + 3);
#pragma unroll
            for (int mt = 0; mt < 2; mt++) {
                float v0 = fmaxf(acc[mt][nt][0] + bA, 0.f);
                float v1 = fmaxf(acc[mt][nt][1] + bB, 0.f);
                float v2 = fmaxf(acc[mt][nt][2] + bA, 0.f);
                float v3 = fmaxf(acc[mt][nt][3] + bB, 0.f);
                pd[mt][0][0] += v0 * w0a + v1 * w1a;
                pd[mt][0][1] += v0 * w0b + v1 * w1b;
                pd[mt][1][0] += v2 * w0a + v3 * w1a;
                pd[mt][1][1] += v2 * w0b + v3 * w1b;
            }
        }
        // reduce over tig (lanes differing in low 2 bits)
#pragma unroll
        for (int a = 0; a < 2; a++)
#pragma unroll
            for (int b = 0; b < 2; b++)
#pragma unroll
                for (int l = 0; l < 2; l++) {
                    pd[a][b][l] += __shfl_xor_sync(0xffffffffu, pd[a][b][l], 1);
                    pd[a][b][l] += __shfl_xor_sync(0xffffffffu, pd[a][b][l], 2);
                }
        if (tig == 0) {
#pragma unroll
            for (int mt = 0; mt < 2; mt++) {
                s_dpart[mt * 16 + gid][wid][0]     = pd[mt][0][0];
                s_dpart[mt * 16 + gid][wid][1]     = pd[mt][0][1];
                s_dpart[mt * 16 + gid + 8][wid][0] = pd[mt][1][0];
                s_dpart[mt * 16 + gid + 8][wid][1] = pd[mt][1][1];
            }
        }
    }
    __syncthreads();

    // logits reduce + softmax (32 threads)
    if (t < 32) {
        float a0 = __ldg(bf3 + 0), a1 = __ldg(bf3 + 1);
#pragma unroll
        for (int w = 0; w < 8; w++) {
            a0 += s_dpart[t][w][0];
            a1 += s_dpart[t][w][1];
        }
        float m = fmaxf(a0, a1);
        float e0 = expf(a0 - m), e1 = expf(a1 - m);
        float inv = 1.f / (e0 + e1);
        s_gate[t][0] = e0 * inv;
        s_gate[t][1] = e1 * inv;
    }
    __syncthreads();

    // stage E
    const float4* feat4 = (const float4*)feat;
    for (int i = t; i < 32 * 32; i += 256) {
        int r = i >> 5, c4 = i & 31;
        int gr = row0 + r;
        if (gr < nP) {
            float4 f = feat4[(size_t)gr * 32 + c4];
            float g0 = s_gate[r][0], g1 = s_gate[r][1];
            int c0 = c4 * 4;
            ushort4 hs = *(const ushort4*)&r3[r * PB256 + c0];
            ushort4 ls = *(const ushort4*)&r3[LO256 + r * PB256 + c0];
            ushort4 hc = *(const ushort4*)&r3[r * PB256 + c0 + 128];
            ushort4 lc = *(const ushort4*)&r3[LO256 + r * PB256 + c0 + 128];
            float4 o;
            o.x = fmaxf((bfu(hs.x) + bfu(ls.x)) * g0 + (bfu(hc.x) + bfu(lc.x)) * g1 + f.x, 0.f);
            o.y = fmaxf((bfu(hs.y) + bfu(ls.y)) * g0 + (bfu(hc.y) + bfu(lc.y)) * g1 + f.y, 0.f);
            o.z = fmaxf((bfu(hs.z) + bfu(ls.z)) * g0 + (bfu(hc.z) + bfu(lc.z)) * g1 + f.z, 0.f);
            o.w = fmaxf((bfu(hs.w) + bfu(ls.w)) * g0 + (bfu(hc.w) + bfu(lc.w)) * g1 + f.w, 0.f);
            ((float4*)out)[(size_t)gr * 32 + c4] = o;
        }
    }
}

// ---------------------------------------------------------------------------
extern "C" void kernel_launch(void* const* d_in, const int* in_sizes, int n_in,
                              void* d_out, int out_size) {
    const float* feat   = (const float*)d_in[0];
    const float* edge_w = (const float*)d_in[1];
    const float* Wself  = (const float*)d_in[2];
    const float* bself  = (const float*)d_in[3];
    const float* Wclu   = (const float*)d_in[4];
    const float* bclu   = (const float*)d_in[5];
    const float* Wh1    = (const float*)d_in[6];
    const float* bh1    = (const float*)d_in[7];
    const float* Wh2    = (const float*)d_in[8];
    const float* bh2    = (const float*)d_in[9];
    const float* Wfuse  = (const float*)d_in[10];
    const float* Wf1    = (const float*)d_in[11];
    const float* bf1    = (const float*)d_in[12];
    const float* Wf2    = (const float*)d_in[13];
    const float* bf2    = (const float*)d_in[14];
    const float* Wf3    = (const float*)d_in[15];
    const float* bf3    = (const float*)d_in[16];
    const int*   e_pid  = (const int*)d_in[17];
    const int*   e_hid  = (const int*)d_in[18];

    int nE = in_sizes[17];
    int nP = in_sizes[0] / D_IN;
    float* out = (float*)d_out;

    int zpN = N_HE * (D_IN / 4);
    zero_pack_kernel<<<(zpN + 255) / 256, 256>>>(Wself, Wclu, Wf1, Wf2, Wh1);

    fill_kernel<<<(nE + 255) / 256, 256>>>(edge_w, e_pid, e_hid, feat, nE);

    zero_cluster_kernel<<<592, 256>>>();

    he_acc_kernel<<<(N_HE + 7) / 8, 256>>>(feat);

    attn_gemm_kernel<<<(N_HE + 31) / 32, 256>>>(bh1, Wh2, bh2, Wfuse);

    ovf_kernel<<<8, 256>>>();

    p_acc_kernel<<<(nP + 7) / 8, 256>>>(nP);

    size_t smemBytes = (size_t)SMEM_U16 * 2;
    cudaFuncSetAttribute(mlp2_kernel, cudaFuncAttributeMaxDynamicSharedMemorySize,
                         (int)smemBytes);
    int nBlocks = (nP + 31) / 32;
    mlp2_kernel<<<nBlocks, 256, smemBytes>>>(feat, bself, bclu, bf1, bf2,
                                             Wf3, bf3, out, nP);
}